// round 4
// baseline (speedup 1.0000x reference)
#include <cuda_runtime.h>
#include <math.h>

#define BSZ 1024
#define PP  128
#define SSZ 128
#define NNODE 168
#define NHH 4
#define HGG 128

// ---------------- static scratch (allocation-free rule) ----------------
__device__ float g_Xf[BSZ*PP*40];            // features (b,128,40), normalized in place
__device__ float g_T1[BSZ*40*64];
__device__ float g_As[BSZ*40*40];
__device__ float g_T2[BSZ*PP*64];
__device__ float g_At[BSZ*PP*PP];
__device__ float g_Ms[BSZ*40*PP];
__device__ float g_Mt[BSZ*PP*40];
__device__ float g_H [BSZ*NNODE*HGG];        // (b,168,128)
__device__ float g_Q [BSZ*NHH*NNODE*HGG];
__device__ float g_K [BSZ*NHH*NNODE*HGG];
__device__ float g_V [BSZ*NHH*NNODE*HGG];
__device__ float g_S [BSZ*NHH*NNODE*NNODE];  // scores / attn
__device__ float g_O [BSZ*NHH*NNODE*HGG];

// ---------------- block reduction helpers (128 threads) ----------------
__device__ __forceinline__ float4 bsum4(float4 v, float4* red){
    int tid = threadIdx.x;
    __syncthreads();
    red[tid] = v;
    __syncthreads();
    #pragma unroll
    for (int o = 64; o > 0; o >>= 1){
        if (tid < o){
            float4 a = red[tid], b = red[tid+o];
            a.x += b.x; a.y += b.y; a.z += b.z; a.w += b.w;
            red[tid] = a;
        }
        __syncthreads();
    }
    return red[0];
}

__device__ __forceinline__ float2 bmax2(float2 v, float4* red){
    int tid = threadIdx.x;
    __syncthreads();
    red[tid] = make_float4(v.x, v.y, 0.f, 0.f);
    __syncthreads();
    #pragma unroll
    for (int o = 64; o > 0; o >>= 1){
        if (tid < o){
            red[tid].x = fmaxf(red[tid].x, red[tid+o].x);
            red[tid].y = fmaxf(red[tid].y, red[tid+o].y);
        }
        __syncthreads();
    }
    return make_float2(red[0].x, red[0].y);
}

// ---------------- K1: per-row feature extraction ----------------
// grid = BSZ*PP blocks, 128 threads. Writes columns 0..19 of g_Xf.
__global__ void feat_kernel(const float* __restrict__ X, float* __restrict__ Xf){
    __shared__ float s[128], ctab[128], stab[128], psd[128], av[128];
    __shared__ float4 red[128];
    __shared__ float sel[2];
    int row = blockIdx.x;
    int tid = threadIdx.x;

    float x = X[(size_t)row*128 + tid];
    s[tid] = x;
    float sv, cv;
    sincospif((float)tid * (1.0f/64.0f), &sv, &cv);   // 2*pi*tid/128
    ctab[tid] = cv; stab[tid] = sv;

    float2 mm2 = bmax2(make_float2(x, -x), red);
    float mx = mm2.x, mn = -mm2.y;

    float xc  = fminf(fmaxf(x, -0.99999988f), 0.99999988f); // fp32(1-1e-7)
    float asn = asinf(xc);
    float atn = atanf(x);
    float4 r1 = bsum4(make_float4(x, x*x, asn, atn), red);
    float mean    = r1.x * (1.0f/128.0f);
    float rms     = sqrtf(r1.y * (1.0f/128.0f));
    float mean_as = r1.z * (1.0f/128.0f);
    float mean_at = r1.w * (1.0f/128.0f);

    float cen = x - mean;
    float c2  = cen*cen;
    float e   = expf(x - mx);
    float4 r2 = bsum4(make_float4(c2, c2*cen, c2*c2, e), red);
    float var  = r2.x * (1.0f/127.0f);
    float stdv = sqrtf(var);
    float se   = r2.w;

    float da = asn - mean_as, dt = atn - mean_at;
    float4 r3 = bsum4(make_float4(e*x, da*da, dt*dt, 0.f), red);
    float ent      = (mx + logf(se)) - r3.x / se;      // lse - sum(p*s)
    float std_asin = sqrtf(r3.y * (1.0f/127.0f));
    float std_atan = sqrtf(r3.z * (1.0f/127.0f));
    float kurt = (r2.z * (1.0f/128.0f)) / (var*var)  - 3.0f;
    float skew = (r2.y * (1.0f/128.0f)) / (var*stdv);

    // half DFT, exact conjugate-symmetric mirror
    if (tid <= 64){
        float re = 0.f, im = 0.f;
        int j = 0;
        #pragma unroll 8
        for (int t = 0; t < 128; ++t){
            float st = s[t];
            re += st * ctab[j];
            im -= st * stab[j];
            j = (j + tid) & 127;
        }
        float a2 = re*re + im*im;
        av[tid]  = sqrtf(a2);
        psd[tid] = a2 * (1.0f/128.0f);
    }
    __syncthreads();
    if (tid > 64){ psd[tid] = psd[128-tid]; av[tid] = av[128-tid]; }
    __syncthreads();

    float pj = psd[tid];
    float aj = av[tid];
    float fj = (float)((tid < 64) ? tid : tid - 128) * (1.0f/128.0f);
    float4 r4 = bsum4(make_float4(pj, pj*pj, fj*pj, 0.f), red);
    float psum      = r4.x;
    float mean_freq = r4.z / psum;
    float pbw       = sqrtf(r4.y / psum);
    float2 m2 = bmax2(make_float2(pj, aj), red);
    float max_psd = m2.x, max_amp = m2.y;

    // stable-argsort rank 64 (median) and first-occurrence argmax
    int rank = 0, gc = 0;
    #pragma unroll 4
    for (int i = 0; i < 128; ++i){
        float pi = psd[i];
        rank += (pi < pj) || (pi == pj && i < tid);
        float ai = av[i];
        gc   += (ai > aj) || (ai == aj && i < tid);
    }
    if (rank == 64) sel[0] = fj;
    if (gc == 0)    sel[1] = fj;
    __syncthreads();

    if (tid == 0){
        float* o = Xf + (size_t)row*40;
        o[0]=mx; o[1]=mn; o[2]=stdv; o[3]=rms; o[4]=mean; o[5]=mx-mn; o[6]=var;
        o[7]=ent; o[8]=std_asin; o[9]=std_atan; o[10]=kurt; o[11]=skew;
        o[12]=mean_freq; o[13]=sel[0]; o[14]=psum; o[15]=1.0f; o[16]=pbw;
        o[17]=max_psd; o[18]=max_amp; o[19]=sel[1];
    }
}

// ---------------- K2: cumsum features + per-batch L2 normalization ----------------
__global__ void cum_norm_kernel(float* __restrict__ Xf){
    __shared__ float red[256];
    int b = blockIdx.x;
    float* F = Xf + (size_t)b*5120;
    int tid = threadIdx.x;
    if (tid < 20){
        float c = 0.f;
        for (int p = 0; p < 128; ++p){
            c += F[p*40 + tid];
            F[p*40 + 20 + tid] = c / sqrtf(fmaxf(fabsf(c), 1e-12f));
        }
    }
    __syncthreads();
    float ss = 0.f;
    for (int i = tid; i < 5120; i += 256){ float v = F[i]; ss += v*v; }
    red[tid] = ss; __syncthreads();
    #pragma unroll
    for (int o = 128; o > 0; o >>= 1){ if (tid < o) red[tid] += red[tid+o]; __syncthreads(); }
    float inv = 1.0f / sqrtf(red[0]);
    for (int i = tid; i < 5120; i += 256) F[i] *= inv;
}

// ---------------- generic strided batched GEMM ----------------
// C[z] = act(alpha * A[z'] (MxK) @ B[z''] (KxN) + bias)
// A batch index = (aDiv>1 ? z/aDiv : z); B/bias batch index = (bMod==0 ? z : z%bMod)
__global__ void bgemm(
    const float* __restrict__ A, long long sAb, int sAr, int sAc, int aDiv,
    const float* __restrict__ B, long long sBb, int sBr, int sBc, int bMod,
    const float* __restrict__ bias, int biasStride,
    float* __restrict__ C, long long sCb, int ldc,
    int M, int N, int K, float alpha, int act)
{
    __shared__ float As[16][33], Bs[16][33];
    int z = blockIdx.z;
    const float* Ab = A + (size_t)((aDiv > 1) ? (z / aDiv) : z) * (size_t)sAb;
    const float* Bb = B + (size_t)((bMod == 0) ? z : (z % bMod)) * (size_t)sBb;
    const float* biasb = bias ? (bias + (size_t)((bMod > 1) ? (z % bMod) : 0) * (size_t)biasStride) : (const float*)0;
    float* Cb = C + (size_t)z * (size_t)sCb;

    int row0 = blockIdx.y * 32, col0 = blockIdx.x * 32;
    int tx = threadIdx.x, ty = threadIdx.y;
    int tid = ty*16 + tx;
    float acc00=0.f, acc01=0.f, acc10=0.f, acc11=0.f;

    for (int k0 = 0; k0 < K; k0 += 16){
        #pragma unroll
        for (int idx = tid; idx < 512; idx += 256){
            int kk = idx >> 5, mm = idx & 31;
            int gk = k0 + kk;
            int gm = row0 + mm;
            As[kk][mm] = (gm < M && gk < K) ? Ab[(size_t)gm*sAr + (size_t)gk*sAc] : 0.f;
            int gn = col0 + mm;
            Bs[kk][mm] = (gn < N && gk < K) ? Bb[(size_t)gk*sBr + (size_t)gn*sBc] : 0.f;
        }
        __syncthreads();
        #pragma unroll
        for (int kk = 0; kk < 16; ++kk){
            float a0 = As[kk][ty], a1 = As[kk][ty+16];
            float b0 = Bs[kk][tx], b1 = Bs[kk][tx+16];
            acc00 += a0*b0; acc01 += a0*b1; acc10 += a1*b0; acc11 += a1*b1;
        }
        __syncthreads();
    }

    float vals[2][2] = {{acc00, acc01},{acc10, acc11}};
    #pragma unroll
    for (int i = 0; i < 2; ++i){
        int gm = row0 + ty + i*16;
        if (gm >= M) continue;
        #pragma unroll
        for (int j = 0; j < 2; ++j){
            int gn = col0 + tx + j*16;
            if (gn >= N) continue;
            float v = vals[i][j] * alpha;
            if (biasb) v += biasb[gn];
            if (act == 1)      v = tanhf(v);
            else if (act == 2) v = (v >= 0.f) ? v : 0.01f*v;
            Cb[(size_t)gm*ldc + gn] = v;
        }
    }
}

// ---------------- softmax over rows of length 168 ----------------
__global__ void softmax_kernel(float* __restrict__ S){
    __shared__ float red[256];
    size_t r = blockIdx.x;
    float* row = S + r * 168;
    int tid = threadIdx.x;
    float v = (tid < 168) ? row[tid] : -3.4e38f;
    red[tid] = v; __syncthreads();
    #pragma unroll
    for (int o = 128; o > 0; o >>= 1){ if (tid < o) red[tid] = fmaxf(red[tid], red[tid+o]); __syncthreads(); }
    float mx = red[0]; __syncthreads();
    float e = (tid < 168) ? expf(v - mx) : 0.f;
    red[tid] = e; __syncthreads();
    #pragma unroll
    for (int o = 128; o > 0; o >>= 1){ if (tid < o) red[tid] += red[tid+o]; __syncthreads(); }
    float s = red[0];
    if (tid < 168) row[tid] = e / s;
}

// ---------------- final FC: out[b] = O_flat . fc_w + fc_b ----------------
__global__ void fc_kernel(const float* __restrict__ O, const float* __restrict__ fcw,
                          const float* __restrict__ fcb, float* __restrict__ out){
    __shared__ float red[256];
    int b = blockIdx.x;
    const float* Ob = O + (size_t)b * 86016;
    int tid = threadIdx.x;
    float acc = 0.f;
    for (int i = tid; i < 86016; i += 256){
        int h = i / 21504;
        int r2 = i - h*21504;
        int n = r2 >> 7, e = r2 & 127;
        acc += Ob[i] * fcw[n*512 + h*128 + e];   // transpose(0,2,1,3) flatten
    }
    red[tid] = acc; __syncthreads();
    #pragma unroll
    for (int o = 128; o > 0; o >>= 1){ if (tid < o) red[tid] += red[tid+o]; __syncthreads(); }
    if (tid == 0) out[b] = red[0] + fcb[0];
}

// ---------------- host launcher ----------------
extern "C" void kernel_launch(void* const* d_in, const int* in_sizes, int n_in,
                              void* d_out, int out_size){
    const float* X      = (const float*)d_in[0];
    const float* spa_w1 = (const float*)d_in[1];
    const float* spa_b1 = (const float*)d_in[2];
    const float* spa_w2 = (const float*)d_in[3];
    const float* spa_b2 = (const float*)d_in[4];
    const float* tem_w1 = (const float*)d_in[5];
    const float* tem_b1 = (const float*)d_in[6];
    const float* tem_w2 = (const float*)d_in[7];
    const float* tem_b2 = (const float*)d_in[8];
    const float* sgnn_w = (const float*)d_in[9];
    const float* sgnn_b = (const float*)d_in[10];
    const float* tgnn_w = (const float*)d_in[11];
    const float* tgnn_b = (const float*)d_in[12];
    const float* q_w    = (const float*)d_in[13];
    const float* q_b    = (const float*)d_in[14];
    const float* k_w    = (const float*)d_in[15];
    const float* k_b    = (const float*)d_in[16];
    const float* v_w    = (const float*)d_in[17];
    const float* v_b    = (const float*)d_in[18];
    const float* fc_w   = (const float*)d_in[19];
    const float* fc_b   = (const float*)d_in[20];
    float* out = (float*)d_out;

    float *Xf,*T1,*As_,*T2,*At,*Ms,*Mt,*H,*Q,*Kb,*V,*S,*O;
    cudaGetSymbolAddress((void**)&Xf,  g_Xf);
    cudaGetSymbolAddress((void**)&T1,  g_T1);
    cudaGetSymbolAddress((void**)&As_, g_As);
    cudaGetSymbolAddress((void**)&T2,  g_T2);
    cudaGetSymbolAddress((void**)&At,  g_At);
    cudaGetSymbolAddress((void**)&Ms,  g_Ms);
    cudaGetSymbolAddress((void**)&Mt,  g_Mt);
    cudaGetSymbolAddress((void**)&H,   g_H);
    cudaGetSymbolAddress((void**)&Q,   g_Q);
    cudaGetSymbolAddress((void**)&Kb,  g_K);
    cudaGetSymbolAddress((void**)&V,   g_V);
    cudaGetSymbolAddress((void**)&S,   g_S);
    cudaGetSymbolAddress((void**)&O,   g_O);

    const float inv_sqrt_hg = 0.08838834764831845f; // 1/sqrt(128)

    // K1: features
    feat_kernel<<<BSZ*PP, 128>>>(X, Xf);
    // K2: cumsum + normalize
    cum_norm_kernel<<<BSZ, 256>>>(Xf);

    dim3 thr(16,16);
    // (a) T1 = tanh(Xt @ spa_w1 + spa_b1)   (40x128)@(128x64)
    bgemm<<<dim3(2,2,BSZ), thr>>>(Xf, 5120, 1, 40, 1,  spa_w1, 0, 64, 1, 1,
                                  spa_b1, 0,  T1, 2560, 64,  40, 64, 128, 1.f, 1);
    // (b) A_s = T1 @ spa_w2 + spa_b2       (40x64)@(64x40)
    bgemm<<<dim3(2,2,BSZ), thr>>>(T1, 2560, 64, 1, 1,  spa_w2, 0, 40, 1, 1,
                                  spa_b2, 0,  As_, 1600, 40,  40, 40, 64, 1.f, 0);
    // (c) T2 = tanh(Xf @ tem_w1 + tem_b1)  (128x40)@(40x64)
    bgemm<<<dim3(2,4,BSZ), thr>>>(Xf, 5120, 40, 1, 1,  tem_w1, 0, 64, 1, 1,
                                  tem_b1, 0,  T2, 8192, 64,  128, 64, 40, 1.f, 1);
    // (d) A_t = T2 @ tem_w2 + tem_b2       (128x64)@(64x128)
    bgemm<<<dim3(4,4,BSZ), thr>>>(T2, 8192, 64, 1, 1,  tem_w2, 0, 128, 1, 1,
                                  tem_b2, 0,  At, 16384, 128,  128, 128, 64, 1.f, 0);
    // (e) M_s = A_s @ Xt                   (40x40)@(40x128), B batched transposed
    bgemm<<<dim3(4,2,BSZ), thr>>>(As_, 1600, 40, 1, 1,  Xf, 5120, 1, 40, 0,
                                  (const float*)0, 0,  Ms, 5120, 128,  40, 128, 40, 1.f, 0);
    // (f) H_s = leaky(M_s @ sgnn_w + b)    (40x128)@(128x128) -> H rows 0..39
    bgemm<<<dim3(4,2,BSZ), thr>>>(Ms, 5120, 128, 1, 1,  sgnn_w, 0, 128, 1, 1,
                                  sgnn_b, 0,  H, 21504, 128,  40, 128, 128, 1.f, 2);
    // (g) M_t = A_t @ Xf                   (128x128)@(128x40), B batched
    bgemm<<<dim3(2,4,BSZ), thr>>>(At, 16384, 128, 1, 1,  Xf, 5120, 40, 1, 0,
                                  (const float*)0, 0,  Mt, 5120, 40,  128, 40, 128, 1.f, 0);
    // (h) H_t = leaky(M_t @ tgnn_w + b)    (128x40)@(40x128) -> H rows 40..167
    bgemm<<<dim3(4,4,BSZ), thr>>>(Mt, 5120, 40, 1, 1,  tgnn_w, 0, 128, 1, 1,
                                  tgnn_b, 0,  H + 40*128, 21504, 128,  128, 128, 40, 1.f, 2);

    // (i) Q/K/V  (168x128)@(128x128) per (b,h); z = b*4+h
    bgemm<<<dim3(4,6,BSZ*NHH), thr>>>(H, 21504, 128, 1, 4,  q_w, 16384, 128, 1, 4,
                                      q_b, 128,  Q, 21504, 128,  168, 128, 128, 1.f, 0);
    bgemm<<<dim3(4,6,BSZ*NHH), thr>>>(H, 21504, 128, 1, 4,  k_w, 16384, 128, 1, 4,
                                      k_b, 128,  Kb, 21504, 128,  168, 128, 128, 1.f, 0);
    bgemm<<<dim3(4,6,BSZ*NHH), thr>>>(H, 21504, 128, 1, 4,  v_w, 16384, 128, 1, 4,
                                      v_b, 128,  V, 21504, 128,  168, 128, 128, 1.f, 0);

    // (j) scores = Q @ K^T / sqrt(128)     (168x128)@(128x168)
    bgemm<<<dim3(6,6,BSZ*NHH), thr>>>(Q, 21504, 128, 1, 1,  Kb, 21504, 1, 128, 0,
                                      (const float*)0, 0,  S, 28224, 168,  168, 168, 128, inv_sqrt_hg, 0);
    // (k) softmax rows
    softmax_kernel<<<BSZ*NHH*NNODE, 256>>>(S);
    // (l) O = attn @ V                     (168x168)@(168x128)
    bgemm<<<dim3(4,6,BSZ*NHH), thr>>>(S, 28224, 168, 1, 1,  V, 21504, 128, 1, 0,
                                      (const float*)0, 0,  O, 21504, 128,  168, 128, 168, 1.f, 0);
    // (m) final FC
    fc_kernel<<<BSZ, 256>>>(O, fc_w, fc_b, out);
}

// round 6
// speedup vs baseline: 1.6598x; 1.6598x over previous
#include <cuda_runtime.h>
#include <math.h>

#define BSZ 1024
#define PP  128
#define SSZ 128
#define NNODE 168
#define NHH 4
#define HGG 128

// ---------------- static scratch (allocation-free rule) ----------------
__device__ float g_Xf[BSZ*PP*40];            // features (b,128,40), normalized in place
__device__ float g_T1[BSZ*40*64];
__device__ float g_As[BSZ*40*40];
__device__ float g_T2[BSZ*PP*64];
__device__ float g_At[BSZ*PP*PP];
__device__ float g_Ms[BSZ*40*PP];
__device__ float g_Mt[BSZ*PP*40];
__device__ float g_H [BSZ*NNODE*HGG];        // (b,168,128)
__device__ float g_Q [BSZ*NHH*NNODE*HGG];
__device__ float g_K [BSZ*NHH*NNODE*HGG];
__device__ float g_V [BSZ*NHH*NNODE*HGG];
__device__ float g_S [BSZ*NHH*NNODE*NNODE];  // scores / attn
__device__ float g_O [BSZ*NHH*NNODE*HGG];

// ---------------- block reduction helpers (128 threads) ----------------
__device__ __forceinline__ float4 bsum4(float4 v, float4* red){
    int tid = threadIdx.x;
    __syncthreads();
    red[tid] = v;
    __syncthreads();
    #pragma unroll
    for (int o = 64; o > 0; o >>= 1){
        if (tid < o){
            float4 a = red[tid], b = red[tid+o];
            a.x += b.x; a.y += b.y; a.z += b.z; a.w += b.w;
            red[tid] = a;
        }
        __syncthreads();
    }
    return red[0];
}

__device__ __forceinline__ float2 bmax2(float2 v, float4* red){
    int tid = threadIdx.x;
    __syncthreads();
    red[tid] = make_float4(v.x, v.y, 0.f, 0.f);
    __syncthreads();
    #pragma unroll
    for (int o = 64; o > 0; o >>= 1){
        if (tid < o){
            red[tid].x = fmaxf(red[tid].x, red[tid+o].x);
            red[tid].y = fmaxf(red[tid].y, red[tid+o].y);
        }
        __syncthreads();
    }
    return make_float2(red[0].x, red[0].y);
}

// ---------------- K1: per-row feature extraction ----------------
__global__ void feat_kernel(const float* __restrict__ X, float* __restrict__ Xf){
    __shared__ float s[128], ctab[128], stab[128], psd[128], av[128];
    __shared__ float4 red[128];
    __shared__ float sel[2];
    int row = blockIdx.x;
    int tid = threadIdx.x;

    float x = X[(size_t)row*128 + tid];
    s[tid] = x;
    float sv, cv;
    sincospif((float)tid * (1.0f/64.0f), &sv, &cv);   // 2*pi*tid/128
    ctab[tid] = cv; stab[tid] = sv;

    float2 mm2 = bmax2(make_float2(x, -x), red);
    float mx = mm2.x, mn = -mm2.y;

    float xc  = fminf(fmaxf(x, -0.99999988f), 0.99999988f); // fp32(1-1e-7)
    float asn = asinf(xc);
    float atn = atanf(x);
    float4 r1 = bsum4(make_float4(x, x*x, asn, atn), red);
    float mean    = r1.x * (1.0f/128.0f);
    float rms     = sqrtf(r1.y * (1.0f/128.0f));
    float mean_as = r1.z * (1.0f/128.0f);
    float mean_at = r1.w * (1.0f/128.0f);

    float cen = x - mean;
    float c2  = cen*cen;
    float e   = expf(x - mx);
    float4 r2 = bsum4(make_float4(c2, c2*cen, c2*c2, e), red);
    float var  = r2.x * (1.0f/127.0f);
    float stdv = sqrtf(var);
    float se   = r2.w;

    float da = asn - mean_as, dt = atn - mean_at;
    float4 r3 = bsum4(make_float4(e*x, da*da, dt*dt, 0.f), red);
    float ent      = (mx + logf(se)) - r3.x / se;
    float std_asin = sqrtf(r3.y * (1.0f/127.0f));
    float std_atan = sqrtf(r3.z * (1.0f/127.0f));
    float kurt = (r2.z * (1.0f/128.0f)) / (var*var)  - 3.0f;
    float skew = (r2.y * (1.0f/128.0f)) / (var*stdv);

    // half DFT, exact conjugate-symmetric mirror
    if (tid <= 64){
        float re = 0.f, im = 0.f;
        int j = 0;
        #pragma unroll 8
        for (int t = 0; t < 128; ++t){
            float st = s[t];
            re += st * ctab[j];
            im -= st * stab[j];
            j = (j + tid) & 127;
        }
        float a2 = re*re + im*im;
        av[tid]  = sqrtf(a2);
        psd[tid] = a2 * (1.0f/128.0f);
    }
    __syncthreads();
    if (tid > 64){ psd[tid] = psd[128-tid]; av[tid] = av[128-tid]; }
    __syncthreads();

    float pj = psd[tid];
    float aj = av[tid];
    float fj = (float)((tid < 64) ? tid : tid - 128) * (1.0f/128.0f);
    float4 r4 = bsum4(make_float4(pj, pj*pj, fj*pj, 0.f), red);
    float psum      = r4.x;
    float mean_freq = r4.z / psum;
    float pbw       = sqrtf(r4.y / psum);
    float2 m2 = bmax2(make_float2(pj, aj), red);
    float max_psd = m2.x, max_amp = m2.y;

    // stable-argsort rank 64 (median) and first-occurrence argmax
    int rank = 0, gc = 0;
    #pragma unroll 4
    for (int i = 0; i < 128; ++i){
        float pi = psd[i];
        rank += (pi < pj) || (pi == pj && i < tid);
        float ai = av[i];
        gc   += (ai > aj) || (ai == aj && i < tid);
    }
    if (rank == 64) sel[0] = fj;
    if (gc == 0)    sel[1] = fj;
    __syncthreads();

    if (tid == 0){
        float* o = Xf + (size_t)row*40;
        o[0]=mx; o[1]=mn; o[2]=stdv; o[3]=rms; o[4]=mean; o[5]=mx-mn; o[6]=var;
        o[7]=ent; o[8]=std_asin; o[9]=std_atan; o[10]=kurt; o[11]=skew;
        o[12]=mean_freq; o[13]=sel[0]; o[14]=psum; o[15]=1.0f; o[16]=pbw;
        o[17]=max_psd; o[18]=max_amp; o[19]=sel[1];
    }
}

// ---------------- K2: cumsum features + per-batch L2 normalization ----------------
__global__ void cum_norm_kernel(float* __restrict__ Xf){
    __shared__ float red[256];
    int b = blockIdx.x;
    float* F = Xf + (size_t)b*5120;
    int tid = threadIdx.x;
    if (tid < 20){
        float c = 0.f;
        for (int p = 0; p < 128; ++p){
            c += F[p*40 + tid];
            F[p*40 + 20 + tid] = c / sqrtf(fmaxf(fabsf(c), 1e-12f));
        }
    }
    __syncthreads();
    float ss = 0.f;
    for (int i = tid; i < 5120; i += 256){ float v = F[i]; ss += v*v; }
    red[tid] = ss; __syncthreads();
    #pragma unroll
    for (int o = 128; o > 0; o >>= 1){ if (tid < o) red[tid] += red[tid+o]; __syncthreads(); }
    float inv = 1.0f / sqrtf(red[0]);
    for (int i = tid; i < 5120; i += 256) F[i] *= inv;
}

// ---------------- templated strided batched GEMM ----------------
// C[z] = act(alpha * A[z'] (MxK) @ B[z''] (KxN) + bias)
// A batch index = (aDiv>1 ? z/aDiv : z); B/bias batch index = (bMod==0 ? z : z%bMod)
template<int BM, int BN, int BK, int TM, int TN>
__global__ void bgemm_t(
    const float* __restrict__ A, long long sAb, int sAr, int sAc, int aDiv,
    const float* __restrict__ B, long long sBb, int sBr, int sBc, int bMod,
    const float* __restrict__ bias, int biasStride,
    float* __restrict__ C, long long sCb, int ldc,
    int M, int N, int K, float alpha, int act)
{
    constexpr int TPN = BN / TN;            // threads along N
    constexpr int TPM = BM / TM;            // threads along M
    constexpr int NT  = TPN * TPM;          // threads per block
    __shared__ float As[BK][BM+4];
    __shared__ float Bs[BK][BN+4];

    int z = blockIdx.z;
    const float* Ab = A + (size_t)((aDiv > 1) ? (z / aDiv) : z) * (size_t)sAb;
    const float* Bb = B + (size_t)((bMod == 0) ? z : (z % bMod)) * (size_t)sBb;
    const float* biasb = bias ? (bias + (size_t)((bMod > 1) ? (z % bMod) : 0) * (size_t)biasStride) : (const float*)0;
    float* Cb = C + (size_t)z * (size_t)sCb;

    int row0 = blockIdx.y * BM, col0 = blockIdx.x * BN;
    int tid = threadIdx.x;
    int tx = tid % TPN, ty = tid / TPN;

    float acc[TM][TN];
    #pragma unroll
    for (int i = 0; i < TM; ++i)
        #pragma unroll
        for (int j = 0; j < TN; ++j) acc[i][j] = 0.f;

    for (int k0 = 0; k0 < K; k0 += BK){
        #pragma unroll
        for (int i = tid; i < BM*BK; i += NT){
            int kk = i / BM, mm = i % BM;
            int gm = row0 + mm, gk = k0 + kk;
            As[kk][mm] = (gm < M && gk < K) ? Ab[(size_t)gm*sAr + (size_t)gk*sAc] : 0.f;
        }
        #pragma unroll
        for (int i = tid; i < BN*BK; i += NT){
            int kk = i / BN, nn = i % BN;
            int gn = col0 + nn, gk = k0 + kk;
            Bs[kk][nn] = (gn < N && gk < K) ? Bb[(size_t)gk*sBr + (size_t)gn*sBc] : 0.f;
        }
        __syncthreads();
        #pragma unroll
        for (int kk = 0; kk < BK; ++kk){
            float a[TM], b[TN];
            #pragma unroll
            for (int i = 0; i < TM; i += 4)
                *(float4*)&a[i] = *(const float4*)&As[kk][ty*TM + i];
            #pragma unroll
            for (int j = 0; j < TN; j += 4)
                *(float4*)&b[j] = *(const float4*)&Bs[kk][tx*TN + j];
            #pragma unroll
            for (int i = 0; i < TM; ++i)
                #pragma unroll
                for (int j = 0; j < TN; ++j)
                    acc[i][j] += a[i]*b[j];
        }
        __syncthreads();
    }

    #pragma unroll
    for (int i = 0; i < TM; ++i){
        int gm = row0 + ty*TM + i;
        if (gm >= M) continue;
        #pragma unroll
        for (int j = 0; j < TN; ++j){
            int gn = col0 + tx*TN + j;
            if (gn >= N) continue;
            float v = acc[i][j] * alpha;
            if (biasb) v += biasb[gn];
            if (act == 1)      v = tanhf(v);
            else if (act == 2) v = (v >= 0.f) ? v : 0.01f*v;
            Cb[(size_t)gm*ldc + gn] = v;
        }
    }
}

// G1: 64x128 tile, 4x8 micro, 256 threads (big-N shapes)
// G2: 64x64 tile, 8x4 micro, 128 threads (N in {40,64,168})
#define G1 bgemm_t<64,128,16,4,8>
#define G2 bgemm_t<64,64,16,8,4>

// ---------------- softmax over rows of length 168 ----------------
__global__ void softmax_kernel(float* __restrict__ S){
    __shared__ float red[256];
    size_t r = blockIdx.x;
    float* row = S + r * 168;
    int tid = threadIdx.x;
    float v = (tid < 168) ? row[tid] : -3.4e38f;
    red[tid] = v; __syncthreads();
    #pragma unroll
    for (int o = 128; o > 0; o >>= 1){ if (tid < o) red[tid] = fmaxf(red[tid], red[tid+o]); __syncthreads(); }
    float mx = red[0]; __syncthreads();
    float e = (tid < 168) ? expf(v - mx) : 0.f;
    red[tid] = e; __syncthreads();
    #pragma unroll
    for (int o = 128; o > 0; o >>= 1){ if (tid < o) red[tid] += red[tid+o]; __syncthreads(); }
    float s = red[0];
    if (tid < 168) row[tid] = e / s;
}

// ---------------- final FC: out[b] = O_flat . fc_w + fc_b ----------------
__global__ void fc_kernel(const float* __restrict__ O, const float* __restrict__ fcw,
                          const float* __restrict__ fcb, float* __restrict__ out){
    __shared__ float red[256];
    int b = blockIdx.x;
    const float* Ob = O + (size_t)b * 86016;
    int tid = threadIdx.x;
    float acc = 0.f;
    for (int i = tid; i < 86016; i += 256){
        int h = i / 21504;
        int r2 = i - h*21504;
        int n = r2 >> 7, e = r2 & 127;
        acc += Ob[i] * fcw[n*512 + h*128 + e];   // transpose(0,2,1,3) flatten
    }
    red[tid] = acc; __syncthreads();
    #pragma unroll
    for (int o = 128; o > 0; o >>= 1){ if (tid < o) red[tid] += red[tid+o]; __syncthreads(); }
    if (tid == 0) out[b] = red[0] + fcb[0];
}

// ---------------- host launcher ----------------
extern "C" void kernel_launch(void* const* d_in, const int* in_sizes, int n_in,
                              void* d_out, int out_size){
    const float* X      = (const float*)d_in[0];
    const float* spa_w1 = (const float*)d_in[1];
    const float* spa_b1 = (const float*)d_in[2];
    const float* spa_w2 = (const float*)d_in[3];
    const float* spa_b2 = (const float*)d_in[4];
    const float* tem_w1 = (const float*)d_in[5];
    const float* tem_b1 = (const float*)d_in[6];
    const float* tem_w2 = (const float*)d_in[7];
    const float* tem_b2 = (const float*)d_in[8];
    const float* sgnn_w = (const float*)d_in[9];
    const float* sgnn_b = (const float*)d_in[10];
    const float* tgnn_w = (const float*)d_in[11];
    const float* tgnn_b = (const float*)d_in[12];
    const float* q_w    = (const float*)d_in[13];
    const float* q_b    = (const float*)d_in[14];
    const float* k_w    = (const float*)d_in[15];
    const float* k_b    = (const float*)d_in[16];
    const float* v_w    = (const float*)d_in[17];
    const float* v_b    = (const float*)d_in[18];
    const float* fc_w   = (const float*)d_in[19];
    const float* fc_b   = (const float*)d_in[20];
    float* out = (float*)d_out;

    float *Xf,*T1,*As_,*T2,*At,*Ms,*Mt,*H,*Q,*Kb,*V,*S,*O;
    cudaGetSymbolAddress((void**)&Xf,  g_Xf);
    cudaGetSymbolAddress((void**)&T1,  g_T1);
    cudaGetSymbolAddress((void**)&As_, g_As);
    cudaGetSymbolAddress((void**)&T2,  g_T2);
    cudaGetSymbolAddress((void**)&At,  g_At);
    cudaGetSymbolAddress((void**)&Ms,  g_Ms);
    cudaGetSymbolAddress((void**)&Mt,  g_Mt);
    cudaGetSymbolAddress((void**)&H,   g_H);
    cudaGetSymbolAddress((void**)&Q,   g_Q);
    cudaGetSymbolAddress((void**)&Kb,  g_K);
    cudaGetSymbolAddress((void**)&V,   g_V);
    cudaGetSymbolAddress((void**)&S,   g_S);
    cudaGetSymbolAddress((void**)&O,   g_O);

    const float inv_sqrt_hg = 0.08838834764831845f; // 1/sqrt(128)

    // K1: features
    feat_kernel<<<BSZ*PP, 128>>>(X, Xf);
    // K2: cumsum + normalize
    cum_norm_kernel<<<BSZ, 256>>>(Xf);

    // (a) T1 = tanh(Xt @ spa_w1 + spa_b1)   (40x128)@(128x64)
    G2<<<dim3(1,1,BSZ), 128>>>(Xf, 5120, 1, 40, 1,  spa_w1, 0, 64, 1, 1,
                               spa_b1, 0,  T1, 2560, 64,  40, 64, 128, 1.f, 1);
    // (b) A_s = T1 @ spa_w2 + spa_b2       (40x64)@(64x40)
    G2<<<dim3(1,1,BSZ), 128>>>(T1, 2560, 64, 1, 1,  spa_w2, 0, 40, 1, 1,
                               spa_b2, 0,  As_, 1600, 40,  40, 40, 64, 1.f, 0);
    // (c) T2 = tanh(Xf @ tem_w1 + tem_b1)  (128x40)@(40x64)
    G2<<<dim3(1,2,BSZ), 128>>>(Xf, 5120, 40, 1, 1,  tem_w1, 0, 64, 1, 1,
                               tem_b1, 0,  T2, 8192, 64,  128, 64, 40, 1.f, 1);
    // (d) A_t = T2 @ tem_w2 + tem_b2       (128x64)@(64x128)
    G1<<<dim3(1,2,BSZ), 256>>>(T2, 8192, 64, 1, 1,  tem_w2, 0, 128, 1, 1,
                               tem_b2, 0,  At, 16384, 128,  128, 128, 64, 1.f, 0);
    // (e) M_s = A_s @ Xt                   (40x40)@(40x128), B batched transposed
    G1<<<dim3(1,1,BSZ), 256>>>(As_, 1600, 40, 1, 1,  Xf, 5120, 1, 40, 0,
                               (const float*)0, 0,  Ms, 5120, 128,  40, 128, 40, 1.f, 0);
    // (f) H_s = leaky(M_s @ sgnn_w + b)    (40x128)@(128x128) -> H rows 0..39
    G1<<<dim3(1,1,BSZ), 256>>>(Ms, 5120, 128, 1, 1,  sgnn_w, 0, 128, 1, 1,
                               sgnn_b, 0,  H, 21504, 128,  40, 128, 128, 1.f, 2);
    // (g) M_t = A_t @ Xf                   (128x128)@(128x40), B batched
    G2<<<dim3(1,2,BSZ), 128>>>(At, 16384, 128, 1, 1,  Xf, 5120, 40, 1, 0,
                               (const float*)0, 0,  Mt, 5120, 40,  128, 40, 128, 1.f, 0);
    // (h) H_t = leaky(M_t @ tgnn_w + b)    (128x40)@(40x128) -> H rows 40..167
    G1<<<dim3(1,2,BSZ), 256>>>(Mt, 5120, 40, 1, 1,  tgnn_w, 0, 128, 1, 1,
                               tgnn_b, 0,  H + 40*128, 21504, 128,  128, 128, 40, 1.f, 2);

    // (i) Q/K/V  (168x128)@(128x128) per (b,h); z = b*4+h
    G1<<<dim3(1,3,BSZ*NHH), 256>>>(H, 21504, 128, 1, 4,  q_w, 16384, 128, 1, 4,
                                   q_b, 128,  Q, 21504, 128,  168, 128, 128, 1.f, 0);
    G1<<<dim3(1,3,BSZ*NHH), 256>>>(H, 21504, 128, 1, 4,  k_w, 16384, 128, 1, 4,
                                   k_b, 128,  Kb, 21504, 128,  168, 128, 128, 1.f, 0);
    G1<<<dim3(1,3,BSZ*NHH), 256>>>(H, 21504, 128, 1, 4,  v_w, 16384, 128, 1, 4,
                                   v_b, 128,  V, 21504, 128,  168, 128, 128, 1.f, 0);

    // (j) scores = Q @ K^T / sqrt(128)     (168x128)@(128x168)
    G2<<<dim3(3,3,BSZ*NHH), 128>>>(Q, 21504, 128, 1, 1,  Kb, 21504, 1, 128, 0,
                                   (const float*)0, 0,  S, 28224, 168,  168, 168, 128, inv_sqrt_hg, 0);
    // (k) softmax rows
    softmax_kernel<<<BSZ*NHH*NNODE, 256>>>(S);
    // (l) O = attn @ V                     (168x168)@(168x128)
    G1<<<dim3(1,3,BSZ*NHH), 256>>>(S, 28224, 168, 1, 1,  V, 21504, 128, 1, 0,
                                   (const float*)0, 0,  O, 21504, 128,  168, 128, 168, 1.f, 0);
    // (m) final FC
    fc_kernel<<<BSZ, 256>>>(O, fc_w, fc_b, out);
}

// round 7
// speedup vs baseline: 1.9367x; 1.1668x over previous
#include <cuda_runtime.h>
#include <math.h>

#define BSZ 1024
#define PP  128
#define SSZ 128
#define NNODE 168
#define NHH 4
#define HGG 128

// ---------------- static scratch (allocation-free rule) ----------------
__device__ float g_Xf[BSZ*PP*40];            // features (b,128,40), normalized in place
__device__ float g_T1[BSZ*40*64];
__device__ float g_As[BSZ*40*40];
__device__ float g_T2[BSZ*PP*64];
__device__ float g_At[BSZ*PP*PP];
__device__ float g_Ms[BSZ*40*PP];
__device__ float g_Mt[BSZ*PP*40];
__device__ float g_H [BSZ*NNODE*HGG];        // (b,168,128)
__device__ float g_Q [BSZ*NHH*NNODE*HGG];
__device__ float g_K [BSZ*NHH*NNODE*HGG];
__device__ float g_V [BSZ*NHH*NNODE*HGG];
__device__ float g_S [BSZ*NHH*NNODE*NNODE];  // scores / attn
__device__ float g_O [BSZ*NHH*NNODE*HGG];

// ---------------- block reduction helpers (128 threads) ----------------
__device__ __forceinline__ float4 bsum4(float4 v, float4* red){
    int tid = threadIdx.x;
    __syncthreads();
    red[tid] = v;
    __syncthreads();
    #pragma unroll
    for (int o = 64; o > 0; o >>= 1){
        if (tid < o){
            float4 a = red[tid], b = red[tid+o];
            a.x += b.x; a.y += b.y; a.z += b.z; a.w += b.w;
            red[tid] = a;
        }
        __syncthreads();
    }
    return red[0];
}

__device__ __forceinline__ float2 bmax2(float2 v, float4* red){
    int tid = threadIdx.x;
    __syncthreads();
    red[tid] = make_float4(v.x, v.y, 0.f, 0.f);
    __syncthreads();
    #pragma unroll
    for (int o = 64; o > 0; o >>= 1){
        if (tid < o){
            red[tid].x = fmaxf(red[tid].x, red[tid+o].x);
            red[tid].y = fmaxf(red[tid].y, red[tid+o].y);
        }
        __syncthreads();
    }
    return make_float2(red[0].x, red[0].y);
}

// ---------------- K1: per-row feature extraction ----------------
__global__ void feat_kernel(const float* __restrict__ X, float* __restrict__ Xf){
    __shared__ float s[128], ctab[128], stab[128], psd[128], av[128];
    __shared__ float4 red[128];
    __shared__ float sel[2];
    int row = blockIdx.x;
    int tid = threadIdx.x;

    float x = X[(size_t)row*128 + tid];
    s[tid] = x;
    float sv, cv;
    sincospif((float)tid * (1.0f/64.0f), &sv, &cv);   // 2*pi*tid/128
    ctab[tid] = cv; stab[tid] = sv;

    float2 mm2 = bmax2(make_float2(x, -x), red);
    float mx = mm2.x, mn = -mm2.y;

    float xc  = fminf(fmaxf(x, -0.99999988f), 0.99999988f); // fp32(1-1e-7)
    float asn = asinf(xc);
    float atn = atanf(x);
    float4 r1 = bsum4(make_float4(x, x*x, asn, atn), red);
    float mean    = r1.x * (1.0f/128.0f);
    float rms     = sqrtf(r1.y * (1.0f/128.0f));
    float mean_as = r1.z * (1.0f/128.0f);
    float mean_at = r1.w * (1.0f/128.0f);

    float cen = x - mean;
    float c2  = cen*cen;
    float e   = expf(x - mx);
    float4 r2 = bsum4(make_float4(c2, c2*cen, c2*c2, e), red);
    float var  = r2.x * (1.0f/127.0f);
    float stdv = sqrtf(var);
    float se   = r2.w;

    float da = asn - mean_as, dt = atn - mean_at;
    float4 r3 = bsum4(make_float4(e*x, da*da, dt*dt, 0.f), red);
    float ent      = (mx + logf(se)) - r3.x / se;
    float std_asin = sqrtf(r3.y * (1.0f/127.0f));
    float std_atan = sqrtf(r3.z * (1.0f/127.0f));
    float kurt = (r2.z * (1.0f/128.0f)) / (var*var)  - 3.0f;
    float skew = (r2.y * (1.0f/128.0f)) / (var*stdv);

    // half DFT, exact conjugate-symmetric mirror
    if (tid <= 64){
        float re = 0.f, im = 0.f;
        int j = 0;
        #pragma unroll 8
        for (int t = 0; t < 128; ++t){
            float st = s[t];
            re += st * ctab[j];
            im -= st * stab[j];
            j = (j + tid) & 127;
        }
        float a2 = re*re + im*im;
        av[tid]  = sqrtf(a2);
        psd[tid] = a2 * (1.0f/128.0f);
    }
    __syncthreads();
    if (tid > 64){ psd[tid] = psd[128-tid]; av[tid] = av[128-tid]; }
    __syncthreads();

    float pj = psd[tid];
    float aj = av[tid];
    float fj = (float)((tid < 64) ? tid : tid - 128) * (1.0f/128.0f);
    float4 r4 = bsum4(make_float4(pj, pj*pj, fj*pj, 0.f), red);
    float psum      = r4.x;
    float mean_freq = r4.z / psum;
    float pbw       = sqrtf(r4.y / psum);
    float2 m2 = bmax2(make_float2(pj, aj), red);
    float max_psd = m2.x, max_amp = m2.y;

    // stable-argsort rank 64 (median) and first-occurrence argmax
    int rank = 0, gc = 0;
    #pragma unroll 4
    for (int i = 0; i < 128; ++i){
        float pi = psd[i];
        rank += (pi < pj) || (pi == pj && i < tid);
        float ai = av[i];
        gc   += (ai > aj) || (ai == aj && i < tid);
    }
    if (rank == 64) sel[0] = fj;
    if (gc == 0)    sel[1] = fj;
    __syncthreads();

    if (tid == 0){
        float* o = Xf + (size_t)row*40;
        o[0]=mx; o[1]=mn; o[2]=stdv; o[3]=rms; o[4]=mean; o[5]=mx-mn; o[6]=var;
        o[7]=ent; o[8]=std_asin; o[9]=std_atan; o[10]=kurt; o[11]=skew;
        o[12]=mean_freq; o[13]=sel[0]; o[14]=psum; o[15]=1.0f; o[16]=pbw;
        o[17]=max_psd; o[18]=max_amp; o[19]=sel[1];
    }
}

// ---------------- K2: cumsum features + per-batch L2 normalization ----------------
__global__ void cum_norm_kernel(float* __restrict__ Xf){
    __shared__ float red[256];
    int b = blockIdx.x;
    float* F = Xf + (size_t)b*5120;
    int tid = threadIdx.x;
    if (tid < 20){
        float c = 0.f;
        for (int p = 0; p < 128; ++p){
            c += F[p*40 + tid];
            F[p*40 + 20 + tid] = c / sqrtf(fmaxf(fabsf(c), 1e-12f));
        }
    }
    __syncthreads();
    float ss = 0.f;
    for (int i = tid; i < 5120; i += 256){ float v = F[i]; ss += v*v; }
    red[tid] = ss; __syncthreads();
    #pragma unroll
    for (int o = 128; o > 0; o >>= 1){ if (tid < o) red[tid] += red[tid+o]; __syncthreads(); }
    float inv = 1.0f / sqrtf(red[0]);
    for (int i = tid; i < 5120; i += 256) F[i] *= inv;
}

// ---------------- templated strided batched GEMM, double-buffered ----------------
// C[z] = act(alpha * A[z'] (MxK) @ B[z''] (KxN) + bias)
// A batch index = (aDiv>1 ? z/aDiv : z); B/bias batch index = (bMod==0 ? z : z%bMod)
template<int BM, int BN, int BK, int TM, int TN>
__global__ void bgemm_t(
    const float* __restrict__ A, long long sAb, int sAr, int sAc, int aDiv,
    const float* __restrict__ B, long long sBb, int sBr, int sBc, int bMod,
    const float* __restrict__ bias, int biasStride,
    float* __restrict__ C, long long sCb, int ldc,
    int M, int N, int K, float alpha, int act)
{
    constexpr int TPN = BN / TN;            // threads along N
    constexpr int TPM = BM / TM;            // threads along M
    constexpr int NT  = TPN * TPM;          // threads per block
    constexpr int AL  = (BM*BK)/NT;         // per-thread A stage elems
    constexpr int BL  = (BN*BK)/NT;         // per-thread B stage elems
    __shared__ float As[2][BK][BM+4];
    __shared__ float Bs[2][BK][BN+4];

    int z = blockIdx.z;
    const float* Ab = A + (size_t)((aDiv > 1) ? (z / aDiv) : z) * (size_t)sAb;
    const float* Bb = B + (size_t)((bMod == 0) ? z : (z % bMod)) * (size_t)sBb;
    const float* biasb = bias ? (bias + (size_t)((bMod > 1) ? (z % bMod) : 0) * (size_t)biasStride) : (const float*)0;
    float* Cb = C + (size_t)z * (size_t)sCb;

    int row0 = blockIdx.y * BM, col0 = blockIdx.x * BN;
    int tid = threadIdx.x;
    int tx = tid % TPN, ty = tid / TPN;

    float acc[TM][TN];
    #pragma unroll
    for (int i = 0; i < TM; ++i)
        #pragma unroll
        for (int j = 0; j < TN; ++j) acc[i][j] = 0.f;

    float ra[AL], rb[BL];

    // prefetch tile 0 into registers
    #pragma unroll
    for (int u = 0; u < AL; ++u){
        int i = tid + u*NT;
        int kk = i / BM, mm = i % BM;
        int gm = row0 + mm, gk = kk;
        ra[u] = (gm < M && gk < K) ? Ab[(size_t)gm*sAr + (size_t)gk*sAc] : 0.f;
    }
    #pragma unroll
    for (int u = 0; u < BL; ++u){
        int i = tid + u*NT;
        int kk = i / BN, nn = i % BN;
        int gn = col0 + nn, gk = kk;
        rb[u] = (gn < N && gk < K) ? Bb[(size_t)gk*sBr + (size_t)gn*sBc] : 0.f;
    }
    #pragma unroll
    for (int u = 0; u < AL; ++u){
        int i = tid + u*NT;
        As[0][i / BM][i % BM] = ra[u];
    }
    #pragma unroll
    for (int u = 0; u < BL; ++u){
        int i = tid + u*NT;
        Bs[0][i / BN][i % BN] = rb[u];
    }
    __syncthreads();

    int nk = (K + BK - 1) / BK;
    for (int t = 0; t < nk; ++t){
        int cur = t & 1, nxt = cur ^ 1;
        // prefetch next tile into registers (overlaps with compute below)
        if (t + 1 < nk){
            int k0 = (t + 1) * BK;
            #pragma unroll
            for (int u = 0; u < AL; ++u){
                int i = tid + u*NT;
                int kk = i / BM, mm = i % BM;
                int gm = row0 + mm, gk = k0 + kk;
                ra[u] = (gm < M && gk < K) ? Ab[(size_t)gm*sAr + (size_t)gk*sAc] : 0.f;
            }
            #pragma unroll
            for (int u = 0; u < BL; ++u){
                int i = tid + u*NT;
                int kk = i / BN, nn = i % BN;
                int gn = col0 + nn, gk = k0 + kk;
                rb[u] = (gn < N && gk < K) ? Bb[(size_t)gk*sBr + (size_t)gn*sBc] : 0.f;
            }
        }
        // compute on current stage
        #pragma unroll
        for (int kk = 0; kk < BK; ++kk){
            float a[TM], b[TN];
            #pragma unroll
            for (int i = 0; i < TM; i += 4)
                *(float4*)&a[i] = *(const float4*)&As[cur][kk][ty*TM + i];
            #pragma unroll
            for (int j = 0; j < TN; j += 4)
                *(float4*)&b[j] = *(const float4*)&Bs[cur][kk][tx*TN + j];
            #pragma unroll
            for (int i = 0; i < TM; ++i)
                #pragma unroll
                for (int j = 0; j < TN; ++j)
                    acc[i][j] += a[i]*b[j];
        }
        // stage next tile into the other buffer
        if (t + 1 < nk){
            #pragma unroll
            for (int u = 0; u < AL; ++u){
                int i = tid + u*NT;
                As[nxt][i / BM][i % BM] = ra[u];
            }
            #pragma unroll
            for (int u = 0; u < BL; ++u){
                int i = tid + u*NT;
                Bs[nxt][i / BN][i % BN] = rb[u];
            }
        }
        __syncthreads();
    }

    #pragma unroll
    for (int i = 0; i < TM; ++i){
        int gm = row0 + ty*TM + i;
        if (gm >= M) continue;
        #pragma unroll
        for (int j = 0; j < TN; ++j){
            int gn = col0 + tx*TN + j;
            if (gn >= N) continue;
            float v = acc[i][j] * alpha;
            if (biasb) v += biasb[gn];
            if (act == 1)      v = tanhf(v);
            else if (act == 2) v = (v >= 0.f) ? v : 0.01f*v;
            Cb[(size_t)gm*ldc + gn] = v;
        }
    }
}

// G1: 64x128 tile, 4x8 micro, 256 threads (big-N shapes)
// G2: 64x64 tile, 8x4 micro, 128 threads (N in {40,64,168})
#define G1 bgemm_t<64,128,16,4,8>
#define G2 bgemm_t<64,64,16,8,4>

// ---------------- softmax over rows of length 168 ----------------
__global__ void softmax_kernel(float* __restrict__ S){
    __shared__ float red[256];
    size_t r = blockIdx.x;
    float* row = S + r * 168;
    int tid = threadIdx.x;
    float v = (tid < 168) ? row[tid] : -3.4e38f;
    red[tid] = v; __syncthreads();
    #pragma unroll
    for (int o = 128; o > 0; o >>= 1){ if (tid < o) red[tid] = fmaxf(red[tid], red[tid+o]); __syncthreads(); }
    float mx = red[0]; __syncthreads();
    float e = (tid < 168) ? expf(v - mx) : 0.f;
    red[tid] = e; __syncthreads();
    #pragma unroll
    for (int o = 128; o > 0; o >>= 1){ if (tid < o) red[tid] += red[tid+o]; __syncthreads(); }
    float s = red[0];
    if (tid < 168) row[tid] = e / s;
}

// ---------------- final FC: out[b] = O_flat . fc_w + fc_b ----------------
__global__ void fc_kernel(const float* __restrict__ O, const float* __restrict__ fcw,
                          const float* __restrict__ fcb, float* __restrict__ out){
    __shared__ float red[256];
    int b = blockIdx.x;
    const float* Ob = O + (size_t)b * 86016;
    int tid = threadIdx.x;
    float acc = 0.f;
    for (int i = tid; i < 86016; i += 256){
        int h = i / 21504;
        int r2 = i - h*21504;
        int n = r2 >> 7, e = r2 & 127;
        acc += Ob[i] * fcw[n*512 + h*128 + e];   // transpose(0,2,1,3) flatten
    }
    red[tid] = acc; __syncthreads();
    #pragma unroll
    for (int o = 128; o > 0; o >>= 1){ if (tid < o) red[tid] += red[tid+o]; __syncthreads(); }
    if (tid == 0) out[b] = red[0] + fcb[0];
}

// ---------------- host launcher ----------------
extern "C" void kernel_launch(void* const* d_in, const int* in_sizes, int n_in,
                              void* d_out, int out_size){
    const float* X      = (const float*)d_in[0];
    const float* spa_w1 = (const float*)d_in[1];
    const float* spa_b1 = (const float*)d_in[2];
    const float* spa_w2 = (const float*)d_in[3];
    const float* spa_b2 = (const float*)d_in[4];
    const float* tem_w1 = (const float*)d_in[5];
    const float* tem_b1 = (const float*)d_in[6];
    const float* tem_w2 = (const float*)d_in[7];
    const float* tem_b2 = (const float*)d_in[8];
    const float* sgnn_w = (const float*)d_in[9];
    const float* sgnn_b = (const float*)d_in[10];
    const float* tgnn_w = (const float*)d_in[11];
    const float* tgnn_b = (const float*)d_in[12];
    const float* q_w    = (const float*)d_in[13];
    const float* q_b    = (const float*)d_in[14];
    const float* k_w    = (const float*)d_in[15];
    const float* k_b    = (const float*)d_in[16];
    const float* v_w    = (const float*)d_in[17];
    const float* v_b    = (const float*)d_in[18];
    const float* fc_w   = (const float*)d_in[19];
    const float* fc_b   = (const float*)d_in[20];
    float* out = (float*)d_out;

    float *Xf,*T1,*As_,*T2,*At,*Ms,*Mt,*H,*Q,*Kb,*V,*S,*O;
    cudaGetSymbolAddress((void**)&Xf,  g_Xf);
    cudaGetSymbolAddress((void**)&T1,  g_T1);
    cudaGetSymbolAddress((void**)&As_, g_As);
    cudaGetSymbolAddress((void**)&T2,  g_T2);
    cudaGetSymbolAddress((void**)&At,  g_At);
    cudaGetSymbolAddress((void**)&Ms,  g_Ms);
    cudaGetSymbolAddress((void**)&Mt,  g_Mt);
    cudaGetSymbolAddress((void**)&H,   g_H);
    cudaGetSymbolAddress((void**)&Q,   g_Q);
    cudaGetSymbolAddress((void**)&Kb,  g_K);
    cudaGetSymbolAddress((void**)&V,   g_V);
    cudaGetSymbolAddress((void**)&S,   g_S);
    cudaGetSymbolAddress((void**)&O,   g_O);

    const float inv_sqrt_hg = 0.08838834764831845f; // 1/sqrt(128)

    // K1: features
    feat_kernel<<<BSZ*PP, 128>>>(X, Xf);
    // K2: cumsum + normalize
    cum_norm_kernel<<<BSZ, 256>>>(Xf);

    // (a) T1 = tanh(Xt @ spa_w1 + spa_b1)   (40x128)@(128x64)
    G2<<<dim3(1,1,BSZ), 128>>>(Xf, 5120, 1, 40, 1,  spa_w1, 0, 64, 1, 1,
                               spa_b1, 0,  T1, 2560, 64,  40, 64, 128, 1.f, 1);
    // (b) A_s = T1 @ spa_w2 + spa_b2       (40x64)@(64x40)
    G2<<<dim3(1,1,BSZ), 128>>>(T1, 2560, 64, 1, 1,  spa_w2, 0, 40, 1, 1,
                               spa_b2, 0,  As_, 1600, 40,  40, 40, 64, 1.f, 0);
    // (c) T2 = tanh(Xf @ tem_w1 + tem_b1)  (128x40)@(40x64)
    G2<<<dim3(1,2,BSZ), 128>>>(Xf, 5120, 40, 1, 1,  tem_w1, 0, 64, 1, 1,
                               tem_b1, 0,  T2, 8192, 64,  128, 64, 40, 1.f, 1);
    // (d) A_t = T2 @ tem_w2 + tem_b2       (128x64)@(64x128)
    G1<<<dim3(1,2,BSZ), 256>>>(T2, 8192, 64, 1, 1,  tem_w2, 0, 128, 1, 1,
                               tem_b2, 0,  At, 16384, 128,  128, 128, 64, 1.f, 0);
    // (e) M_s = A_s @ Xt                   (40x40)@(40x128), B batched transposed
    G1<<<dim3(1,1,BSZ), 256>>>(As_, 1600, 40, 1, 1,  Xf, 5120, 1, 40, 0,
                               (const float*)0, 0,  Ms, 5120, 128,  40, 128, 40, 1.f, 0);
    // (f) H_s = leaky(M_s @ sgnn_w + b)    (40x128)@(128x128) -> H rows 0..39
    G1<<<dim3(1,1,BSZ), 256>>>(Ms, 5120, 128, 1, 1,  sgnn_w, 0, 128, 1, 1,
                               sgnn_b, 0,  H, 21504, 128,  40, 128, 128, 1.f, 2);
    // (g) M_t = A_t @ Xf                   (128x128)@(128x40), B batched
    G2<<<dim3(1,2,BSZ), 128>>>(At, 16384, 128, 1, 1,  Xf, 5120, 40, 1, 0,
                               (const float*)0, 0,  Mt, 5120, 40,  128, 40, 128, 1.f, 0);
    // (h) H_t = leaky(M_t @ tgnn_w + b)    (128x40)@(40x128) -> H rows 40..167
    G1<<<dim3(1,2,BSZ), 256>>>(Mt, 5120, 40, 1, 1,  tgnn_w, 0, 128, 1, 1,
                               tgnn_b, 0,  H + 40*128, 21504, 128,  128, 128, 40, 1.f, 2);

    // (i) Q/K/V  (168x128)@(128x128) per (b,h); z = b*4+h
    G1<<<dim3(1,3,BSZ*NHH), 256>>>(H, 21504, 128, 1, 4,  q_w, 16384, 128, 1, 4,
                                   q_b, 128,  Q, 21504, 128,  168, 128, 128, 1.f, 0);
    G1<<<dim3(1,3,BSZ*NHH), 256>>>(H, 21504, 128, 1, 4,  k_w, 16384, 128, 1, 4,
                                   k_b, 128,  Kb, 21504, 128,  168, 128, 128, 1.f, 0);
    G1<<<dim3(1,3,BSZ*NHH), 256>>>(H, 21504, 128, 1, 4,  v_w, 16384, 128, 1, 4,
                                   v_b, 128,  V, 21504, 128,  168, 128, 128, 1.f, 0);

    // (j) scores = Q @ K^T / sqrt(128)     (168x128)@(128x168)
    G2<<<dim3(3,3,BSZ*NHH), 128>>>(Q, 21504, 128, 1, 1,  Kb, 21504, 1, 128, 0,
                                   (const float*)0, 0,  S, 28224, 168,  168, 168, 128, inv_sqrt_hg, 0);
    // (k) softmax rows
    softmax_kernel<<<BSZ*NHH*NNODE, 256>>>(S);
    // (l) O = attn @ V                     (168x168)@(168x128)
    G1<<<dim3(1,3,BSZ*NHH), 256>>>(S, 28224, 168, 1, 1,  V, 21504, 128, 1, 0,
                                   (const float*)0, 0,  O, 21504, 128,  168, 128, 168, 1.f, 0);
    // (m) final FC
    fc_kernel<<<BSZ, 256>>>(O, fc_w, fc_b, out);
}

// round 8
// speedup vs baseline: 2.4682x; 1.2744x over previous
#include <cuda_runtime.h>
#include <math.h>

#define BSZ 1024
#define PP  128
#define SSZ 128
#define NNODE 168
#define NHH 4
#define HGG 128

// ---------------- static scratch (allocation-free rule) ----------------
__device__ float g_Xf[BSZ*PP*40];            // features (b,128,40), normalized in place
__device__ float g_T1[BSZ*40*64];
__device__ float g_As[BSZ*40*40];
__device__ float g_T2[BSZ*PP*64];
__device__ float g_At[BSZ*PP*PP];
__device__ float g_Ms[BSZ*40*PP];
__device__ float g_Mt[BSZ*PP*40];
__device__ float g_H [BSZ*NNODE*HGG];        // (b,168,128)
__device__ float g_Q [BSZ*NHH*NNODE*HGG];
__device__ float g_K [BSZ*NHH*NNODE*HGG];
__device__ float g_V [BSZ*NHH*NNODE*HGG];
__device__ float g_S [BSZ*NHH*NNODE*NNODE];  // scores / attn
__device__ float g_O [BSZ*NHH*NNODE*HGG];

// ---------------- block reduction helpers (128 threads) ----------------
__device__ __forceinline__ float4 bsum4(float4 v, float4* red){
    int tid = threadIdx.x;
    __syncthreads();
    red[tid] = v;
    __syncthreads();
    #pragma unroll
    for (int o = 64; o > 0; o >>= 1){
        if (tid < o){
            float4 a = red[tid], b = red[tid+o];
            a.x += b.x; a.y += b.y; a.z += b.z; a.w += b.w;
            red[tid] = a;
        }
        __syncthreads();
    }
    return red[0];
}

__device__ __forceinline__ float2 bmax2(float2 v, float4* red){
    int tid = threadIdx.x;
    __syncthreads();
    red[tid] = make_float4(v.x, v.y, 0.f, 0.f);
    __syncthreads();
    #pragma unroll
    for (int o = 64; o > 0; o >>= 1){
        if (tid < o){
            red[tid].x = fmaxf(red[tid].x, red[tid+o].x);
            red[tid].y = fmaxf(red[tid].y, red[tid+o].y);
        }
        __syncthreads();
    }
    return make_float2(red[0].x, red[0].y);
}

// ---------------- K1: per-row feature extraction ----------------
__global__ void feat_kernel(const float* __restrict__ X, float* __restrict__ Xf){
    __shared__ float s[128], ctab[128], stab[128], psd[128], av[128];
    __shared__ float4 red[128];
    __shared__ float sel[2];
    int row = blockIdx.x;
    int tid = threadIdx.x;

    float x = X[(size_t)row*128 + tid];
    s[tid] = x;
    float sv, cv;
    sincospif((float)tid * (1.0f/64.0f), &sv, &cv);   // 2*pi*tid/128
    ctab[tid] = cv; stab[tid] = sv;

    float2 mm2 = bmax2(make_float2(x, -x), red);
    float mx = mm2.x, mn = -mm2.y;

    float xc  = fminf(fmaxf(x, -0.99999988f), 0.99999988f); // fp32(1-1e-7)
    float asn = asinf(xc);
    float atn = atanf(x);
    float4 r1 = bsum4(make_float4(x, x*x, asn, atn), red);
    float mean    = r1.x * (1.0f/128.0f);
    float rms     = sqrtf(r1.y * (1.0f/128.0f));
    float mean_as = r1.z * (1.0f/128.0f);
    float mean_at = r1.w * (1.0f/128.0f);

    float cen = x - mean;
    float c2  = cen*cen;
    float e   = expf(x - mx);
    float4 r2 = bsum4(make_float4(c2, c2*cen, c2*c2, e), red);
    float var  = r2.x * (1.0f/127.0f);
    float stdv = sqrtf(var);
    float se   = r2.w;

    float da = asn - mean_as, dt = atn - mean_at;
    float4 r3 = bsum4(make_float4(e*x, da*da, dt*dt, 0.f), red);
    float ent      = (mx + logf(se)) - r3.x / se;
    float std_asin = sqrtf(r3.y * (1.0f/127.0f));
    float std_atan = sqrtf(r3.z * (1.0f/127.0f));
    float kurt = (r2.z * (1.0f/128.0f)) / (var*var)  - 3.0f;
    float skew = (r2.y * (1.0f/128.0f)) / (var*stdv);

    // half DFT, exact conjugate-symmetric mirror
    if (tid <= 64){
        float re = 0.f, im = 0.f;
        int j = 0;
        #pragma unroll 8
        for (int t = 0; t < 128; ++t){
            float st = s[t];
            re += st * ctab[j];
            im -= st * stab[j];
            j = (j + tid) & 127;
        }
        float a2 = re*re + im*im;
        av[tid]  = sqrtf(a2);
        psd[tid] = a2 * (1.0f/128.0f);
    }
    __syncthreads();
    if (tid > 64){ psd[tid] = psd[128-tid]; av[tid] = av[128-tid]; }
    __syncthreads();

    float pj = psd[tid];
    float aj = av[tid];
    float fj = (float)((tid < 64) ? tid : tid - 128) * (1.0f/128.0f);
    float4 r4 = bsum4(make_float4(pj, pj*pj, fj*pj, 0.f), red);
    float psum      = r4.x;
    float mean_freq = r4.z / psum;
    float pbw       = sqrtf(r4.y / psum);
    float2 m2 = bmax2(make_float2(pj, aj), red);
    float max_psd = m2.x, max_amp = m2.y;

    // stable-argsort rank 64 (median) and first-occurrence argmax
    int rank = 0, gc = 0;
    #pragma unroll 4
    for (int i = 0; i < 128; ++i){
        float pi = psd[i];
        rank += (pi < pj) || (pi == pj && i < tid);
        float ai = av[i];
        gc   += (ai > aj) || (ai == aj && i < tid);
    }
    if (rank == 64) sel[0] = fj;
    if (gc == 0)    sel[1] = fj;
    __syncthreads();

    if (tid == 0){
        float* o = Xf + (size_t)row*40;
        o[0]=mx; o[1]=mn; o[2]=stdv; o[3]=rms; o[4]=mean; o[5]=mx-mn; o[6]=var;
        o[7]=ent; o[8]=std_asin; o[9]=std_atan; o[10]=kurt; o[11]=skew;
        o[12]=mean_freq; o[13]=sel[0]; o[14]=psum; o[15]=1.0f; o[16]=pbw;
        o[17]=max_psd; o[18]=max_amp; o[19]=sel[1];
    }
}

// ---------------- K2: cumsum features + per-batch L2 normalization ----------------
__global__ void cum_norm_kernel(float* __restrict__ Xf){
    __shared__ float red[256];
    int b = blockIdx.x;
    float* F = Xf + (size_t)b*5120;
    int tid = threadIdx.x;
    if (tid < 20){
        float c = 0.f;
        for (int p = 0; p < 128; ++p){
            c += F[p*40 + tid];
            F[p*40 + 20 + tid] = c / sqrtf(fmaxf(fabsf(c), 1e-12f));
        }
    }
    __syncthreads();
    float ss = 0.f;
    for (int i = tid; i < 5120; i += 256){ float v = F[i]; ss += v*v; }
    red[tid] = ss; __syncthreads();
    #pragma unroll
    for (int o = 128; o > 0; o >>= 1){ if (tid < o) red[tid] += red[tid+o]; __syncthreads(); }
    float inv = 1.0f / sqrtf(red[0]);
    for (int i = tid; i < 5120; i += 256) F[i] *= inv;
}

// ---------------- templated strided batched GEMM, double-buffered, 8x8 micro ----------------
// C[z] = act(alpha * A[z'] (MxK) @ B[z''] (KxN) + bias)
// A batch index = (aDiv>1 ? z/aDiv : z); B/bias batch index = (bMod==0 ? z : z%bMod)
template<int BM, int BN, int BK, int TM, int TN>
__global__ void __launch_bounds__((BM/TM)*(BN/TN)) bgemm_t(
    const float* __restrict__ A, long long sAb, int sAr, int sAc, int aDiv,
    const float* __restrict__ B, long long sBb, int sBr, int sBc, int bMod,
    const float* __restrict__ bias, int biasStride,
    float* __restrict__ C, long long sCb, int ldc,
    int M, int N, int K, float alpha, int act)
{
    constexpr int TPN = BN / TN;            // threads along N
    constexpr int TPM = BM / TM;            // threads along M
    constexpr int NT  = TPN * TPM;          // threads per block
    constexpr int AL  = (BM*BK)/NT;         // per-thread A stage elems
    constexpr int BL  = (BN*BK)/NT;         // per-thread B stage elems
    __shared__ float As[2][BK][BM+4];
    __shared__ float Bs[2][BK][BN+4];

    int z = blockIdx.z;
    const float* Ab = A + (size_t)((aDiv > 1) ? (z / aDiv) : z) * (size_t)sAb;
    const float* Bb = B + (size_t)((bMod == 0) ? z : (z % bMod)) * (size_t)sBb;
    const float* biasb = bias ? (bias + (size_t)((bMod > 1) ? (z % bMod) : 0) * (size_t)biasStride) : (const float*)0;
    float* Cb = C + (size_t)z * (size_t)sCb;

    int row0 = blockIdx.y * BM, col0 = blockIdx.x * BN;
    int tid = threadIdx.x;
    int tx = tid % TPN, ty = tid / TPN;

    float acc[TM][TN];
    #pragma unroll
    for (int i = 0; i < TM; ++i)
        #pragma unroll
        for (int j = 0; j < TN; ++j) acc[i][j] = 0.f;

    float ra[AL], rb[BL];

    // prefetch tile 0 into registers
    #pragma unroll
    for (int u = 0; u < AL; ++u){
        int i = tid + u*NT;
        int kk = i / BM, mm = i % BM;
        int gm = row0 + mm, gk = kk;
        ra[u] = (gm < M && gk < K) ? Ab[(size_t)gm*sAr + (size_t)gk*sAc] : 0.f;
    }
    #pragma unroll
    for (int u = 0; u < BL; ++u){
        int i = tid + u*NT;
        int kk = i / BN, nn = i % BN;
        int gn = col0 + nn, gk = kk;
        rb[u] = (gn < N && gk < K) ? Bb[(size_t)gk*sBr + (size_t)gn*sBc] : 0.f;
    }
    #pragma unroll
    for (int u = 0; u < AL; ++u){
        int i = tid + u*NT;
        As[0][i / BM][i % BM] = ra[u];
    }
    #pragma unroll
    for (int u = 0; u < BL; ++u){
        int i = tid + u*NT;
        Bs[0][i / BN][i % BN] = rb[u];
    }
    __syncthreads();

    int nk = (K + BK - 1) / BK;
    for (int t = 0; t < nk; ++t){
        int cur = t & 1, nxt = cur ^ 1;
        // prefetch next tile into registers (overlaps with compute below)
        if (t + 1 < nk){
            int k0 = (t + 1) * BK;
            #pragma unroll
            for (int u = 0; u < AL; ++u){
                int i = tid + u*NT;
                int kk = i / BM, mm = i % BM;
                int gm = row0 + mm, gk = k0 + kk;
                ra[u] = (gm < M && gk < K) ? Ab[(size_t)gm*sAr + (size_t)gk*sAc] : 0.f;
            }
            #pragma unroll
            for (int u = 0; u < BL; ++u){
                int i = tid + u*NT;
                int kk = i / BN, nn = i % BN;
                int gn = col0 + nn, gk = k0 + kk;
                rb[u] = (gn < N && gk < K) ? Bb[(size_t)gk*sBr + (size_t)gn*sBc] : 0.f;
            }
        }
        // compute on current stage
        #pragma unroll
        for (int kk = 0; kk < BK; ++kk){
            float a[TM], b[TN];
            #pragma unroll
            for (int i = 0; i < TM; i += 4)
                *(float4*)&a[i] = *(const float4*)&As[cur][kk][ty*TM + i];
            #pragma unroll
            for (int j = 0; j < TN; j += 4)
                *(float4*)&b[j] = *(const float4*)&Bs[cur][kk][tx*TN + j];
            #pragma unroll
            for (int i = 0; i < TM; ++i)
                #pragma unroll
                for (int j = 0; j < TN; ++j)
                    acc[i][j] += a[i]*b[j];
        }
        // stage next tile into the other buffer
        if (t + 1 < nk){
            #pragma unroll
            for (int u = 0; u < AL; ++u){
                int i = tid + u*NT;
                As[nxt][i / BM][i % BM] = ra[u];
            }
            #pragma unroll
            for (int u = 0; u < BL; ++u){
                int i = tid + u*NT;
                Bs[nxt][i / BN][i % BN] = rb[u];
            }
        }
        __syncthreads();
    }

    #pragma unroll
    for (int i = 0; i < TM; ++i){
        int gm = row0 + ty*TM + i;
        if (gm >= M) continue;
        #pragma unroll
        for (int j = 0; j < TN; ++j){
            int gn = col0 + tx*TN + j;
            if (gn >= N) continue;
            float v = acc[i][j] * alpha;
            if (biasb) v += biasb[gn];
            if (act == 1)      v = tanhf(v);
            else if (act == 2) v = (v >= 0.f) ? v : 0.01f*v;
            Cb[(size_t)gm*ldc + gn] = v;
        }
    }
}

// G3: 64x128 tile, 8x8 micro, 128 threads (big shapes)
// G4: 64x64 tile, 8x8 micro, 64 threads (small / odd-N shapes)
#define G3 bgemm_t<64,128,8,8,8>
#define G4 bgemm_t<64,64,8,8,8>

// ---------------- warp-per-row softmax over rows of length 168 ----------------
__global__ void softmax_kernel(float* __restrict__ S, int nrows){
    int gw   = (blockIdx.x * blockDim.x + threadIdx.x) >> 5;
    int lane = threadIdx.x & 31;
    if (gw >= nrows) return;
    float* row = S + (size_t)gw * 168;
    float v[6];
    float mx = -3.4e38f;
    #pragma unroll
    for (int u = 0; u < 6; ++u){
        int idx = lane + u*32;
        v[u] = (idx < 168) ? row[idx] : -3.4e38f;
        mx = fmaxf(mx, v[u]);
    }
    #pragma unroll
    for (int o = 16; o > 0; o >>= 1)
        mx = fmaxf(mx, __shfl_xor_sync(0xffffffffu, mx, o));
    float sum = 0.f;
    #pragma unroll
    for (int u = 0; u < 6; ++u){
        v[u] = expf(v[u] - mx);
        sum += v[u];
    }
    #pragma unroll
    for (int o = 16; o > 0; o >>= 1)
        sum += __shfl_xor_sync(0xffffffffu, sum, o);
    float inv = 1.0f / sum;
    #pragma unroll
    for (int u = 0; u < 6; ++u){
        int idx = lane + u*32;
        if (idx < 168) row[idx] = v[u] * inv;
    }
}

// ---------------- final FC: out[b] = O_flat . fc_w + fc_b ----------------
__global__ void fc_kernel(const float* __restrict__ O, const float* __restrict__ fcw,
                          const float* __restrict__ fcb, float* __restrict__ out){
    __shared__ float red[256];
    int b = blockIdx.x;
    const float* Ob = O + (size_t)b * 86016;
    int tid = threadIdx.x;
    float acc = 0.f;
    for (int i = tid; i < 86016; i += 256){
        int h = i / 21504;
        int r2 = i - h*21504;
        int n = r2 >> 7, e = r2 & 127;
        acc += Ob[i] * fcw[n*512 + h*128 + e];   // transpose(0,2,1,3) flatten
    }
    red[tid] = acc; __syncthreads();
    #pragma unroll
    for (int o = 128; o > 0; o >>= 1){ if (tid < o) red[tid] += red[tid+o]; __syncthreads(); }
    if (tid == 0) out[b] = red[0] + fcb[0];
}

// ---------------- host launcher ----------------
extern "C" void kernel_launch(void* const* d_in, const int* in_sizes, int n_in,
                              void* d_out, int out_size){
    const float* X      = (const float*)d_in[0];
    const float* spa_w1 = (const float*)d_in[1];
    const float* spa_b1 = (const float*)d_in[2];
    const float* spa_w2 = (const float*)d_in[3];
    const float* spa_b2 = (const float*)d_in[4];
    const float* tem_w1 = (const float*)d_in[5];
    const float* tem_b1 = (const float*)d_in[6];
    const float* tem_w2 = (const float*)d_in[7];
    const float* tem_b2 = (const float*)d_in[8];
    const float* sgnn_w = (const float*)d_in[9];
    const float* sgnn_b = (const float*)d_in[10];
    const float* tgnn_w = (const float*)d_in[11];
    const float* tgnn_b = (const float*)d_in[12];
    const float* q_w    = (const float*)d_in[13];
    const float* q_b    = (const float*)d_in[14];
    const float* k_w    = (const float*)d_in[15];
    const float* k_b    = (const float*)d_in[16];
    const float* v_w    = (const float*)d_in[17];
    const float* v_b    = (const float*)d_in[18];
    const float* fc_w   = (const float*)d_in[19];
    const float* fc_b   = (const float*)d_in[20];
    float* out = (float*)d_out;

    float *Xf,*T1,*As_,*T2,*At,*Ms,*Mt,*H,*Q,*Kb,*V,*S,*O;
    cudaGetSymbolAddress((void**)&Xf,  g_Xf);
    cudaGetSymbolAddress((void**)&T1,  g_T1);
    cudaGetSymbolAddress((void**)&As_, g_As);
    cudaGetSymbolAddress((void**)&T2,  g_T2);
    cudaGetSymbolAddress((void**)&At,  g_At);
    cudaGetSymbolAddress((void**)&Ms,  g_Ms);
    cudaGetSymbolAddress((void**)&Mt,  g_Mt);
    cudaGetSymbolAddress((void**)&H,   g_H);
    cudaGetSymbolAddress((void**)&Q,   g_Q);
    cudaGetSymbolAddress((void**)&Kb,  g_K);
    cudaGetSymbolAddress((void**)&V,   g_V);
    cudaGetSymbolAddress((void**)&S,   g_S);
    cudaGetSymbolAddress((void**)&O,   g_O);

    const float inv_sqrt_hg = 0.08838834764831845f; // 1/sqrt(128)

    // K1: features
    feat_kernel<<<BSZ*PP, 128>>>(X, Xf);
    // K2: cumsum + normalize
    cum_norm_kernel<<<BSZ, 256>>>(Xf);

    // (a) T1 = tanh(Xt @ spa_w1 + spa_b1)   (40x128)@(128x64)
    G4<<<dim3(1,1,BSZ), 64>>>(Xf, 5120, 1, 40, 1,  spa_w1, 0, 64, 1, 1,
                              spa_b1, 0,  T1, 2560, 64,  40, 64, 128, 1.f, 1);
    // (b) A_s = T1 @ spa_w2 + spa_b2       (40x64)@(64x40)
    G4<<<dim3(1,1,BSZ), 64>>>(T1, 2560, 64, 1, 1,  spa_w2, 0, 40, 1, 1,
                              spa_b2, 0,  As_, 1600, 40,  40, 40, 64, 1.f, 0);
    // (c) T2 = tanh(Xf @ tem_w1 + tem_b1)  (128x40)@(40x64)
    G4<<<dim3(1,2,BSZ), 64>>>(Xf, 5120, 40, 1, 1,  tem_w1, 0, 64, 1, 1,
                              tem_b1, 0,  T2, 8192, 64,  128, 64, 40, 1.f, 1);
    // (d) A_t = T2 @ tem_w2 + tem_b2       (128x64)@(64x128)
    G3<<<dim3(1,2,BSZ), 128>>>(T2, 8192, 64, 1, 1,  tem_w2, 0, 128, 1, 1,
                               tem_b2, 0,  At, 16384, 128,  128, 128, 64, 1.f, 0);
    // (e) M_s = A_s @ Xt                   (40x40)@(40x128), B batched transposed
    G3<<<dim3(1,1,BSZ), 128>>>(As_, 1600, 40, 1, 1,  Xf, 5120, 1, 40, 0,
                               (const float*)0, 0,  Ms, 5120, 128,  40, 128, 40, 1.f, 0);
    // (f) H_s = leaky(M_s @ sgnn_w + b)    (40x128)@(128x128) -> H rows 0..39
    G3<<<dim3(1,1,BSZ), 128>>>(Ms, 5120, 128, 1, 1,  sgnn_w, 0, 128, 1, 1,
                               sgnn_b, 0,  H, 21504, 128,  40, 128, 128, 1.f, 2);
    // (g) M_t = A_t @ Xf                   (128x128)@(128x40), B batched
    G4<<<dim3(1,2,BSZ), 64>>>(At, 16384, 128, 1, 1,  Xf, 5120, 40, 1, 0,
                              (const float*)0, 0,  Mt, 5120, 40,  128, 40, 128, 1.f, 0);
    // (h) H_t = leaky(M_t @ tgnn_w + b)    (128x40)@(40x128) -> H rows 40..167
    G3<<<dim3(1,2,BSZ), 128>>>(Mt, 5120, 40, 1, 1,  tgnn_w, 0, 128, 1, 1,
                               tgnn_b, 0,  H + 40*128, 21504, 128,  128, 128, 40, 1.f, 2);

    // (i) Q/K/V  (168x128)@(128x128) per (b,h); z = b*4+h
    G3<<<dim3(1,3,BSZ*NHH), 128>>>(H, 21504, 128, 1, 4,  q_w, 16384, 128, 1, 4,
                                   q_b, 128,  Q, 21504, 128,  168, 128, 128, 1.f, 0);
    G3<<<dim3(1,3,BSZ*NHH), 128>>>(H, 21504, 128, 1, 4,  k_w, 16384, 128, 1, 4,
                                   k_b, 128,  Kb, 21504, 128,  168, 128, 128, 1.f, 0);
    G3<<<dim3(1,3,BSZ*NHH), 128>>>(H, 21504, 128, 1, 4,  v_w, 16384, 128, 1, 4,
                                   v_b, 128,  V, 21504, 128,  168, 128, 128, 1.f, 0);

    // (j) scores = Q @ K^T / sqrt(128)     (168x128)@(128x168)
    G3<<<dim3(2,3,BSZ*NHH), 128>>>(Q, 21504, 128, 1, 1,  Kb, 21504, 1, 128, 0,
                                   (const float*)0, 0,  S, 28224, 168,  168, 168, 128, inv_sqrt_hg, 0);
    // (k) softmax rows (warp per row)
    {
        int nrows = BSZ*NHH*NNODE;
        int nblk = (nrows*32 + 255) / 256;
        softmax_kernel<<<nblk, 256>>>(S, nrows);
    }
    // (l) O = attn @ V                     (168x168)@(168x128)
    G3<<<dim3(1,3,BSZ*NHH), 128>>>(S, 28224, 168, 1, 1,  V, 21504, 128, 1, 0,
                                   (const float*)0, 0,  O, 21504, 128,  168, 128, 168, 1.f, 0);
    // (m) final FC
    fc_kernel<<<BSZ, 256>>>(O, fc_w, fc_b, out);
}

// round 11
// speedup vs baseline: 2.7906x; 1.1306x over previous
#include <cuda_runtime.h>
#include <math.h>

#define BSZ 1024
#define PP  128
#define SSZ 128
#define NNODE 168
#define NHH 4
#define HGG 128

// ---------------- static scratch (allocation-free rule) ----------------
__device__ float g_Xf[BSZ*PP*40];            // features (b,128,40), normalized in place
__device__ float g_T1[BSZ*40*64];
__device__ float g_As[BSZ*40*40];
__device__ float g_T2[BSZ*PP*64];
__device__ float g_At[BSZ*PP*PP];
__device__ float g_Ms[BSZ*40*PP];
__device__ float g_Mt[BSZ*PP*40];
__device__ float g_H [BSZ*NNODE*HGG];        // (b,168,128)
__device__ float g_Q [BSZ*NHH*NNODE*HGG];
__device__ float g_K [BSZ*NHH*NNODE*HGG];
__device__ float g_V [BSZ*NHH*NNODE*HGG];
__device__ float g_S [BSZ*NHH*NNODE*NNODE];  // scores / attn
__device__ float g_O [BSZ*NHH*NNODE*HGG];

// ---------------- block reduction helpers (128 threads) ----------------
__device__ __forceinline__ float4 bsum4(float4 v, float4* red){
    int tid = threadIdx.x;
    __syncthreads();
    red[tid] = v;
    __syncthreads();
    #pragma unroll
    for (int o = 64; o > 0; o >>= 1){
        if (tid < o){
            float4 a = red[tid], b = red[tid+o];
            a.x += b.x; a.y += b.y; a.z += b.z; a.w += b.w;
            red[tid] = a;
        }
        __syncthreads();
    }
    return red[0];
}

__device__ __forceinline__ float2 bmax2(float2 v, float4* red){
    int tid = threadIdx.x;
    __syncthreads();
    red[tid] = make_float4(v.x, v.y, 0.f, 0.f);
    __syncthreads();
    #pragma unroll
    for (int o = 64; o > 0; o >>= 1){
        if (tid < o){
            red[tid].x = fmaxf(red[tid].x, red[tid+o].x);
            red[tid].y = fmaxf(red[tid].y, red[tid+o].y);
        }
        __syncthreads();
    }
    return make_float2(red[0].x, red[0].y);
}

// ---------------- K1: per-row feature extraction ----------------
__global__ void feat_kernel(const float* __restrict__ X, float* __restrict__ Xf){
    __shared__ float s[128], ctab[128], stab[128], psd[128], av[128];
    __shared__ float4 red[128];
    __shared__ float sel[2];
    int row = blockIdx.x;
    int tid = threadIdx.x;

    float x = X[(size_t)row*128 + tid];
    s[tid] = x;
    float sv, cv;
    sincospif((float)tid * (1.0f/64.0f), &sv, &cv);   // 2*pi*tid/128
    ctab[tid] = cv; stab[tid] = sv;

    float2 mm2 = bmax2(make_float2(x, -x), red);
    float mx = mm2.x, mn = -mm2.y;

    float xc  = fminf(fmaxf(x, -0.99999988f), 0.99999988f); // fp32(1-1e-7)
    float asn = asinf(xc);
    float atn = atanf(x);
    float4 r1 = bsum4(make_float4(x, x*x, asn, atn), red);
    float mean    = r1.x * (1.0f/128.0f);
    float rms     = sqrtf(r1.y * (1.0f/128.0f));
    float mean_as = r1.z * (1.0f/128.0f);
    float mean_at = r1.w * (1.0f/128.0f);

    float cen = x - mean;
    float c2  = cen*cen;
    float e   = expf(x - mx);
    float4 r2 = bsum4(make_float4(c2, c2*cen, c2*c2, e), red);
    float var  = r2.x * (1.0f/127.0f);
    float stdv = sqrtf(var);
    float se   = r2.w;

    float da = asn - mean_as, dt = atn - mean_at;
    float4 r3 = bsum4(make_float4(e*x, da*da, dt*dt, 0.f), red);
    float ent      = (mx + logf(se)) - r3.x / se;
    float std_asin = sqrtf(r3.y * (1.0f/127.0f));
    float std_atan = sqrtf(r3.z * (1.0f/127.0f));
    float kurt = (r2.z * (1.0f/128.0f)) / (var*var)  - 3.0f;
    float skew = (r2.y * (1.0f/128.0f)) / (var*stdv);

    // half DFT, exact conjugate-symmetric mirror
    if (tid <= 64){
        float re = 0.f, im = 0.f;
        int j = 0;
        #pragma unroll 8
        for (int t = 0; t < 128; ++t){
            float st = s[t];
            re += st * ctab[j];
            im -= st * stab[j];
            j = (j + tid) & 127;
        }
        float a2 = re*re + im*im;
        av[tid]  = sqrtf(a2);
        psd[tid] = a2 * (1.0f/128.0f);
    }
    __syncthreads();
    if (tid > 64){ psd[tid] = psd[128-tid]; av[tid] = av[128-tid]; }
    __syncthreads();

    float pj = psd[tid];
    float aj = av[tid];
    float fj = (float)((tid < 64) ? tid : tid - 128) * (1.0f/128.0f);
    float4 r4 = bsum4(make_float4(pj, pj*pj, fj*pj, 0.f), red);
    float psum      = r4.x;
    float mean_freq = r4.z / psum;
    float pbw       = sqrtf(r4.y / psum);
    float2 m2 = bmax2(make_float2(pj, aj), red);
    float max_psd = m2.x, max_amp = m2.y;

    // stable-argsort rank 64 (median) and first-occurrence argmax
    int rank = 0, gc = 0;
    #pragma unroll 4
    for (int i = 0; i < 128; ++i){
        float pi = psd[i];
        rank += (pi < pj) || (pi == pj && i < tid);
        float ai = av[i];
        gc   += (ai > aj) || (ai == aj && i < tid);
    }
    if (rank == 64) sel[0] = fj;
    if (gc == 0)    sel[1] = fj;
    __syncthreads();

    if (tid == 0){
        float* o = Xf + (size_t)row*40;
        o[0]=mx; o[1]=mn; o[2]=stdv; o[3]=rms; o[4]=mean; o[5]=mx-mn; o[6]=var;
        o[7]=ent; o[8]=std_asin; o[9]=std_atan; o[10]=kurt; o[11]=skew;
        o[12]=mean_freq; o[13]=sel[0]; o[14]=psum; o[15]=1.0f; o[16]=pbw;
        o[17]=max_psd; o[18]=max_amp; o[19]=sel[1];
    }
}

// ---------------- K2: cumsum features + per-batch L2 normalization ----------------
__global__ void cum_norm_kernel(float* __restrict__ Xf){
    __shared__ float red[256];
    int b = blockIdx.x;
    float* F = Xf + (size_t)b*5120;
    int tid = threadIdx.x;
    if (tid < 20){
        float c = 0.f;
        for (int p = 0; p < 128; ++p){
            c += F[p*40 + tid];
            F[p*40 + 20 + tid] = c / sqrtf(fmaxf(fabsf(c), 1e-12f));
        }
    }
    __syncthreads();
    float ss = 0.f;
    for (int i = tid; i < 5120; i += 256){ float v = F[i]; ss += v*v; }
    red[tid] = ss; __syncthreads();
    #pragma unroll
    for (int o = 128; o > 0; o >>= 1){ if (tid < o) red[tid] += red[tid+o]; __syncthreads(); }
    float inv = 1.0f / sqrtf(red[0]);
    for (int i = tid; i < 5120; i += 256) F[i] *= inv;
}

// ---------------- templated strided batched GEMM, double-buffered, vectorized ----------------
// C[z] = act(alpha * A[z'] (MxK) @ B[z''] (KxN) + bias)
// AV: A rows contiguous in k (sAc==1). BV: B rows contiguous in n (sBc==1).
// Requires K % BK == 0 (all call sites satisfy; K in {40,64,128,168}, BK=8).
template<int BM, int BN, int BK, int TM, int TN, bool AV, bool BV>
__global__ void __launch_bounds__((BM/TM)*(BN/TN)) bgemm_t(
    const float* __restrict__ A, long long sAb, int sAr, int sAc, int aDiv,
    const float* __restrict__ B, long long sBb, int sBr, int sBc, int bMod,
    const float* __restrict__ bias, int biasStride,
    float* __restrict__ C, long long sCb, int ldc,
    int M, int N, int K, float alpha, int act)
{
    constexpr int TPN = BN / TN;
    constexpr int TPM = BM / TM;
    constexpr int NT  = TPN * TPM;
    constexpr int AL  = (BM*BK)/NT;         // scalar A elems per thread
    constexpr int BL  = (BN*BK)/NT;
    constexpr int AL4 = AL/4;               // vector A loads per thread
    constexpr int BL4 = BL/4;
    constexpr int BK4 = BK/4;
    constexpr int BN4 = BN/4;
    __shared__ float As[2][BK][BM+4];
    __shared__ float Bs[2][BK][BN+4];

    int z = blockIdx.z;
    const float* Ab = A + (size_t)((aDiv > 1) ? (z / aDiv) : z) * (size_t)sAb;
    const float* Bb = B + (size_t)((bMod == 0) ? z : (z % bMod)) * (size_t)sBb;
    const float* biasb = bias ? (bias + (size_t)((bMod > 1) ? (z % bMod) : 0) * (size_t)biasStride) : (const float*)0;
    float* Cb = C + (size_t)z * (size_t)sCb;

    int row0 = blockIdx.y * BM, col0 = blockIdx.x * BN;
    int tid = threadIdx.x;
    int tx = tid % TPN, ty = tid / TPN;

    float acc[TM][TN];
    #pragma unroll
    for (int i = 0; i < TM; ++i)
        #pragma unroll
        for (int j = 0; j < TN; ++j) acc[i][j] = 0.f;

    float4 ra4[AV ? AL4 : 1];
    float  ra [AV ? 1 : AL];
    float4 rb4[BV ? BL4 : 1];
    float  rb [BV ? 1 : BL];

    // ---- load tile at k0 into registers ----
    auto fetch = [&](int k0){
        if constexpr (AV){
            #pragma unroll
            for (int u = 0; u < AL4; ++u){
                int i = tid + u*NT;                 // over BM*BK4 items
                int kk4 = i % BK4, mm = i / BK4;
                int gm = row0 + mm;
                ra4[u] = (gm < M) ? *(const float4*)(Ab + (size_t)gm*sAr + (k0 + kk4*4))
                                  : make_float4(0.f,0.f,0.f,0.f);
            }
        } else {
            #pragma unroll
            for (int u = 0; u < AL; ++u){
                int i = tid + u*NT;
                int kk = i / BM, mm = i % BM;
                int gm = row0 + mm, gk = k0 + kk;
                ra[u] = (gm < M) ? Ab[(size_t)gm*sAr + (size_t)gk*sAc] : 0.f;
            }
        }
        if constexpr (BV){
            #pragma unroll
            for (int u = 0; u < BL4; ++u){
                int i = tid + u*NT;                 // over BK*BN4 items
                int kk = i / BN4, nn4 = i % BN4;
                int gn = col0 + nn4*4, gk = k0 + kk;
                rb4[u] = (gn < N) ? *(const float4*)(Bb + (size_t)gk*sBr + gn)
                                  : make_float4(0.f,0.f,0.f,0.f);
            }
        } else {
            #pragma unroll
            for (int u = 0; u < BL; ++u){
                int i = tid + u*NT;
                int kk = i / BN, nn = i % BN;
                int gn = col0 + nn, gk = k0 + kk;
                rb[u] = (gn < N) ? Bb[(size_t)gk*sBr + (size_t)gn*sBc] : 0.f;
            }
        }
    };
    // ---- store registers into smem stage s ----
    auto stage = [&](int sIdx){
        if constexpr (AV){
            #pragma unroll
            for (int u = 0; u < AL4; ++u){
                int i = tid + u*NT;
                int kk4 = i % BK4, mm = i / BK4;
                As[sIdx][kk4*4+0][mm] = ra4[u].x;
                As[sIdx][kk4*4+1][mm] = ra4[u].y;
                As[sIdx][kk4*4+2][mm] = ra4[u].z;
                As[sIdx][kk4*4+3][mm] = ra4[u].w;
            }
        } else {
            #pragma unroll
            for (int u = 0; u < AL; ++u){
                int i = tid + u*NT;
                As[sIdx][i / BM][i % BM] = ra[u];
            }
        }
        if constexpr (BV){
            #pragma unroll
            for (int u = 0; u < BL4; ++u){
                int i = tid + u*NT;
                int kk = i / BN4, nn4 = i % BN4;
                *(float4*)&Bs[sIdx][kk][nn4*4] = rb4[u];
            }
        } else {
            #pragma unroll
            for (int u = 0; u < BL; ++u){
                int i = tid + u*NT;
                Bs[sIdx][i / BN][i % BN] = rb[u];
            }
        }
    };

    fetch(0);
    stage(0);
    __syncthreads();

    int nk = K / BK;
    for (int t = 0; t < nk; ++t){
        int cur = t & 1, nxt = cur ^ 1;
        if (t + 1 < nk) fetch((t + 1) * BK);
        #pragma unroll
        for (int kk = 0; kk < BK; ++kk){
            float a[TM], b[TN];
            #pragma unroll
            for (int i = 0; i < TM; i += 4)
                *(float4*)&a[i] = *(const float4*)&As[cur][kk][ty*TM + i];
            #pragma unroll
            for (int j = 0; j < TN; j += 4)
                *(float4*)&b[j] = *(const float4*)&Bs[cur][kk][tx*TN + j];
            #pragma unroll
            for (int i = 0; i < TM; ++i)
                #pragma unroll
                for (int j = 0; j < TN; ++j)
                    acc[i][j] += a[i]*b[j];
        }
        if (t + 1 < nk) stage(nxt);
        __syncthreads();
    }

    // ---- vectorized epilogue (N % 4 == 0 at every call site) ----
    #pragma unroll
    for (int i = 0; i < TM; ++i){
        int gm = row0 + ty*TM + i;
        if (gm >= M) continue;
        #pragma unroll
        for (int j4 = 0; j4 < TN; j4 += 4){
            int gn = col0 + tx*TN + j4;
            if (gn >= N) continue;
            float4 v;
            float* vp = &v.x;
            #pragma unroll
            for (int c = 0; c < 4; ++c){
                float w = acc[i][j4+c] * alpha;
                if (biasb) w += biasb[gn+c];
                if (act == 1)      w = tanhf(w);
                else if (act == 2) w = (w >= 0.f) ? w : 0.01f*w;
                vp[c] = w;
            }
            *(float4*)(Cb + (size_t)gm*ldc + gn) = v;
        }
    }
}

// Variants (AV: A contiguous in k; BV: B contiguous in n)
#define GBIG  bgemm_t<64,128,8,8,8,true,true>    // 128 thr
#define GBIGE bgemm_t<64,128,8,8,8,true,false>   // (e)
#define GSML  bgemm_t<64,64,8,8,8,true,true>     // 64 thr
#define GSMLA bgemm_t<64,64,8,8,8,false,true>    // (a): A transposed
#define GSMLJ bgemm_t<64,64,8,8,8,true,false>    // (j): B transposed

// ---------------- warp-per-row softmax over rows of length 168 ----------------
__global__ void softmax_kernel(float* __restrict__ S, int nrows){
    int gw   = (blockIdx.x * blockDim.x + threadIdx.x) >> 5;
    int lane = threadIdx.x & 31;
    if (gw >= nrows) return;
    float* row = S + (size_t)gw * 168;
    float v[6];
    float mx = -3.4e38f;
    #pragma unroll
    for (int u = 0; u < 6; ++u){
        int idx = lane + u*32;
        v[u] = (idx < 168) ? row[idx] : -3.4e38f;
        mx = fmaxf(mx, v[u]);
    }
    #pragma unroll
    for (int o = 16; o > 0; o >>= 1)
        mx = fmaxf(mx, __shfl_xor_sync(0xffffffffu, mx, o));
    float sum = 0.f;
    #pragma unroll
    for (int u = 0; u < 6; ++u){
        v[u] = expf(v[u] - mx);
        sum += v[u];
    }
    #pragma unroll
    for (int o = 16; o > 0; o >>= 1)
        sum += __shfl_xor_sync(0xffffffffu, sum, o);
    float inv = 1.0f / sum;
    #pragma unroll
    for (int u = 0; u < 6; ++u){
        int idx = lane + u*32;
        if (idx < 168) row[idx] = v[u] * inv;
    }
}

// ---------------- final FC: out[b] = O_flat . fc_w + fc_b ----------------
__global__ void fc_kernel(const float* __restrict__ O, const float* __restrict__ fcw,
                          const float* __restrict__ fcb, float* __restrict__ out){
    __shared__ float red[256];
    int b = blockIdx.x;
    const float* Ob = O + (size_t)b * 86016;
    int tid = threadIdx.x;
    float acc = 0.f;
    for (int i = tid; i < 86016; i += 256){
        int h = i / 21504;
        int r2 = i - h*21504;
        int n = r2 >> 7, e = r2 & 127;
        acc += Ob[i] * fcw[n*512 + h*128 + e];   // transpose(0,2,1,3) flatten
    }
    red[tid] = acc; __syncthreads();
    #pragma unroll
    for (int o = 128; o > 0; o >>= 1){ if (tid < o) red[tid] += red[tid+o]; __syncthreads(); }
    if (tid == 0) out[b] = red[0] + fcb[0];
}

// ---------------- host launcher ----------------
extern "C" void kernel_launch(void* const* d_in, const int* in_sizes, int n_in,
                              void* d_out, int out_size){
    const float* X      = (const float*)d_in[0];
    const float* spa_w1 = (const float*)d_in[1];
    const float* spa_b1 = (const float*)d_in[2];
    const float* spa_w2 = (const float*)d_in[3];
    const float* spa_b2 = (const float*)d_in[4];
    const float* tem_w1 = (const float*)d_in[5];
    const float* tem_b1 = (const float*)d_in[6];
    const float* tem_w2 = (const float*)d_in[7];
    const float* tem_b2 = (const float*)d_in[8];
    const float* sgnn_w = (const float*)d_in[9];
    const float* sgnn_b = (const float*)d_in[10];
    const float* tgnn_w = (const float*)d_in[11];
    const float* tgnn_b = (const float*)d_in[12];
    const float* q_w    = (const float*)d_in[13];
    const float* q_b    = (const float*)d_in[14];
    const float* k_w    = (const float*)d_in[15];
    const float* k_b    = (const float*)d_in[16];
    const float* v_w    = (const float*)d_in[17];
    const float* v_b    = (const float*)d_in[18];
    const float* fc_w   = (const float*)d_in[19];
    const float* fc_b   = (const float*)d_in[20];
    float* out = (float*)d_out;

    float *Xf,*T1,*As_,*T2,*At,*Ms,*Mt,*H,*Q,*Kb,*V,*S,*O;
    cudaGetSymbolAddress((void**)&Xf,  g_Xf);
    cudaGetSymbolAddress((void**)&T1,  g_T1);
    cudaGetSymbolAddress((void**)&As_, g_As);
    cudaGetSymbolAddress((void**)&T2,  g_T2);
    cudaGetSymbolAddress((void**)&At,  g_At);
    cudaGetSymbolAddress((void**)&Ms,  g_Ms);
    cudaGetSymbolAddress((void**)&Mt,  g_Mt);
    cudaGetSymbolAddress((void**)&H,   g_H);
    cudaGetSymbolAddress((void**)&Q,   g_Q);
    cudaGetSymbolAddress((void**)&Kb,  g_K);
    cudaGetSymbolAddress((void**)&V,   g_V);
    cudaGetSymbolAddress((void**)&S,   g_S);
    cudaGetSymbolAddress((void**)&O,   g_O);

    const float inv_sqrt_hg = 0.08838834764831845f; // 1/sqrt(128)

    // K1: features
    feat_kernel<<<BSZ*PP, 128>>>(X, Xf);
    // K2: cumsum + normalize
    cum_norm_kernel<<<BSZ, 256>>>(Xf);

    // (a) T1 = tanh(Xt @ spa_w1 + spa_b1)   (40x128)@(128x64), A transposed
    GSMLA<<<dim3(1,1,BSZ), 64>>>(Xf, 5120, 1, 40, 1,  spa_w1, 0, 64, 1, 1,
                                 spa_b1, 0,  T1, 2560, 64,  40, 64, 128, 1.f, 1);
    // (b) A_s = T1 @ spa_w2 + spa_b2       (40x64)@(64x40)
    GSML<<<dim3(1,1,BSZ), 64>>>(T1, 2560, 64, 1, 1,  spa_w2, 0, 40, 1, 1,
                                spa_b2, 0,  As_, 1600, 40,  40, 40, 64, 1.f, 0);
    // (c) T2 = tanh(Xf @ tem_w1 + tem_b1)  (128x40)@(40x64)
    GSML<<<dim3(1,2,BSZ), 64>>>(Xf, 5120, 40, 1, 1,  tem_w1, 0, 64, 1, 1,
                                tem_b1, 0,  T2, 8192, 64,  128, 64, 40, 1.f, 1);
    // (d) A_t = T2 @ tem_w2 + tem_b2       (128x64)@(64x128)
    GBIG<<<dim3(1,2,BSZ), 128>>>(T2, 8192, 64, 1, 1,  tem_w2, 0, 128, 1, 1,
                                 tem_b2, 0,  At, 16384, 128,  128, 128, 64, 1.f, 0);
    // (e) M_s = A_s @ Xt                   (40x40)@(40x128), B batched transposed
    GBIGE<<<dim3(1,1,BSZ), 128>>>(As_, 1600, 40, 1, 1,  Xf, 5120, 1, 40, 0,
                                  (const float*)0, 0,  Ms, 5120, 128,  40, 128, 40, 1.f, 0);
    // (f) H_s = leaky(M_s @ sgnn_w + b)    (40x128)@(128x128) -> H rows 0..39
    GBIG<<<dim3(1,1,BSZ), 128>>>(Ms, 5120, 128, 1, 1,  sgnn_w, 0, 128, 1, 1,
                                 sgnn_b, 0,  H, 21504, 128,  40, 128, 128, 1.f, 2);
    // (g) M_t = A_t @ Xf                   (128x128)@(128x40), B batched
    GSML<<<dim3(1,2,BSZ), 64>>>(At, 16384, 128, 1, 1,  Xf, 5120, 40, 1, 0,
                                (const float*)0, 0,  Mt, 5120, 40,  128, 40, 128, 1.f, 0);
    // (h) H_t = leaky(M_t @ tgnn_w + b)    (128x40)@(40x128) -> H rows 40..167
    GBIG<<<dim3(1,2,BSZ), 128>>>(Mt, 5120, 40, 1, 1,  tgnn_w, 0, 128, 1, 1,
                                 tgnn_b, 0,  H + 40*128, 21504, 128,  128, 128, 40, 1.f, 2);

    // (i) Q/K/V  (168x128)@(128x128) per (b,h); z = b*4+h
    GBIG<<<dim3(1,3,BSZ*NHH), 128>>>(H, 21504, 128, 1, 4,  q_w, 16384, 128, 1, 4,
                                     q_b, 128,  Q, 21504, 128,  168, 128, 128, 1.f, 0);
    GBIG<<<dim3(1,3,BSZ*NHH), 128>>>(H, 21504, 128, 1, 4,  k_w, 16384, 128, 1, 4,
                                     k_b, 128,  Kb, 21504, 128,  168, 128, 128, 1.f, 0);
    GBIG<<<dim3(1,3,BSZ*NHH), 128>>>(H, 21504, 128, 1, 4,  v_w, 16384, 128, 1, 4,
                                     v_b, 128,  V, 21504, 128,  168, 128, 128, 1.f, 0);

    // (j) scores = Q @ K^T / sqrt(128)     (168x128)@(128x168), BN=64 tiles (waste 14% vs 52%)
    GSMLJ<<<dim3(3,3,BSZ*NHH), 64>>>(Q, 21504, 128, 1, 1,  Kb, 21504, 1, 128, 0,
                                     (const float*)0, 0,  S, 28224, 168,  168, 168, 128, inv_sqrt_hg, 0);
    // (k) softmax rows (warp per row)
    {
        int nrows = BSZ*NHH*NNODE;
        int nblk = (nrows*32 + 255) / 256;
        softmax_kernel<<<nblk, 256>>>(S, nrows);
    }
    // (l) O = attn @ V                     (168x168)@(168x128)
    GBIG<<<dim3(1,3,BSZ*NHH), 128>>>(S, 28224, 168, 1, 1,  V, 21504, 128, 1, 0,
                                     (const float*)0, 0,  O, 21504, 128,  168, 128, 168, 1.f, 0);
    // (m) final FC
    fc_kernel<<<BSZ, 256>>>(O, fc_w, fc_b, out);
}